// round 9
// baseline (speedup 1.0000x reference)
#include <cuda_runtime.h>
#include <cuda_bf16.h>
#include <cstdint>
#include <cstddef>

#define NN 50000
#define NE 800000
#define NCHUNK 391

// ---------------- static device scratch ----------------
__device__ int   g_cnt[NN];          // histogram (re-zeroed by k_scan each run)
__device__ int   g_cur[NN];          // scatter cursor (re-zeroed by k_scan)
__device__ int   g_rowptr[NN + 1];
__device__ int   g_bsum[64];
__device__ int   g_scan_done;
__device__ int   g_done[NCHUNK];     // per-128-node-chunk agg completion counters
__device__ __align__(16) int2 g_edge[NE];   // (src, float bits of p)
__device__ float g_invdeg[NN];

// bf16x2-packed tables (u32 each = 2 features)
__device__ __align__(16) unsigned g_uv1 [(size_t)NN * 64];  // conv1 u|v (128 feats)
__device__ __align__(16) unsigned g_h16 [(size_t)NN * 32];
__device__ __align__(16) unsigned g_a16 [(size_t)NN * 32];
__device__ __align__(16) unsigned g_y16 [(size_t)NN * 32];
__device__ __align__(16) unsigned g_acat[(size_t)NN * 64];  // A0|A1 (128 feats)
__device__ __align__(16) unsigned g_uv2 [(size_t)NN * 16];  // conv2 u|v (32 feats)

// fp32 state
__device__ __align__(16) float g_r1  [(size_t)NN * 64];
__device__ __align__(16) float g_hf  [(size_t)NN * 64];
__device__ __align__(16) float g_accf[(size_t)NN * 64];
__device__ __align__(16) float g_r2  [(size_t)NN * 16];

// packed weights
__device__ unsigned g_wc1[128 * 192];
__device__ unsigned g_wcA[96 * 64];
__device__ unsigned g_wcB[96 * 64];
__device__ unsigned g_wc2[32 * 48];

// ---------------- helpers ----------------
__device__ __forceinline__ void gds() {
#if __CUDA_ARCH__ >= 900
    cudaGridDependencySynchronize();
#endif
}
__device__ __forceinline__ void trig() {
#if __CUDA_ARCH__ >= 900
    cudaTriggerProgrammaticLaunchCompletion();
#endif
}
__device__ __forceinline__ unsigned pk(float a, float b) {
    __nv_bfloat162 h = __floats2bfloat162_rn(a, b);
    return *reinterpret_cast<unsigned*>(&h);
}
__device__ __forceinline__ float2 up(unsigned u) {
    __nv_bfloat162 h = *reinterpret_cast<__nv_bfloat162*>(&u);
    return make_float2(__bfloat162float(h.x), __bfloat162float(h.y));
}
__device__ __forceinline__ float bfh(unsigned u, int hi) {
    unsigned short s = hi ? (unsigned short)(u >> 16) : (unsigned short)(u & 0xffff);
    __nv_bfloat16 b = *reinterpret_cast<__nv_bfloat16*>(&s);
    return __bfloat162float(b);
}
__device__ __forceinline__ int rp(int i) {
    return g_rowptr[i] + g_bsum[i >> 10];
}
__device__ __forceinline__ int chunk_expect(int c) { return (c == 390) ? 10 : 16; }

// ---------------- prep: edge histogram + weight pack (independent halves) -------
__global__ void k_prep(const int* __restrict__ dst,
                       const float* __restrict__ W1, const float* __restrict__ R1,
                       const float* __restrict__ Wa, const float* __restrict__ Ra,
                       const float* __restrict__ Wb, const float* __restrict__ Rb,
                       const float* __restrict__ W2, const float* __restrict__ R2) {
    trig();
    gds();
    if (blockIdx.x < 782) {                       // histogram: 4 edges per thread
        int q = blockIdx.x * 256 + threadIdx.x;
        if (q * 4 < NE) {
            int4 d = *reinterpret_cast<const int4*>(dst + q * 4);
            atomicAdd(&g_cnt[d.x], 1);
            atomicAdd(&g_cnt[d.y], 1);
            atomicAdd(&g_cnt[d.z], 1);
            atomicAdd(&g_cnt[d.w], 1);
        }
        return;
    }
    int i = (blockIdx.x - 782) * 256 + threadIdx.x;
    if (i < 24576) {                        // g_wc1 [128][192], K=256
        int k2 = i / 192, c = i % 192;
        int ke = 2 * k2, ko = ke + 1;
        float e, o;
        if (c < 64)       { e = W1[ke * 64 + c];              o = W1[ko * 64 + c]; }
        else if (c < 128) { e = W1[(256 + ke) * 64 + c - 64];  o = W1[(256 + ko) * 64 + c - 64]; }
        else              { e = R1[ke * 64 + c - 128];         o = R1[ko * 64 + c - 128]; }
        g_wc1[i] = pk(e, o);
    } else if (i < 30720) {                 // g_wcA [96][64], K=192
        int j = i - 24576, k2 = j / 64, c = j % 64;
        int ke = 2 * k2, ko = ke + 1;
        float e = (ke < 128) ? Wa[ke * 64 + c] : Ra[(ke - 128) * 64 + c];
        float o = (ko < 128) ? Wa[ko * 64 + c] : Ra[(ko - 128) * 64 + c];
        g_wcA[j] = pk(e, o);
    } else if (i < 36864) {                 // g_wcB
        int j = i - 30720, k2 = j / 64, c = j % 64;
        int ke = 2 * k2, ko = ke + 1;
        float e = (ke < 128) ? Wb[ke * 64 + c] : Rb[(ke - 128) * 64 + c];
        float o = (ko < 128) ? Wb[ko * 64 + c] : Rb[(ko - 128) * 64 + c];
        g_wcB[j] = pk(e, o);
    } else if (i < 38400) {                 // g_wc2 [32][48], K=64
        int j = i - 36864, k2 = j / 48, c = j % 48;
        int ke = 2 * k2, ko = ke + 1;
        float e, o;
        if (c < 16)      { e = W2[ke * 16 + c];              o = W2[ko * 16 + c]; }
        else if (c < 32) { e = W2[(64 + ke) * 16 + c - 16];  o = W2[(64 + ko) * 16 + c - 16]; }
        else             { e = R2[ke * 16 + c - 32];         o = R2[ko * 16 + c - 32]; }
        g_wc2[j] = pk(e, o);
    }
}

// block-local exclusive scan; zero cnt/cur/done; LAST-finishing block's warp 0
// does the 49-entry cross-block scan and resets g_scan_done.
__global__ void k_scan() {
    trig();
    gds();
    __shared__ int ws[32];
    __shared__ int is_last;
    int tid = threadIdx.x, lane = tid & 31, wid = tid >> 5;
    int i = blockIdx.x * 1024 + tid;
    if (blockIdx.x == 0 && tid < NCHUNK) g_done[tid] = 0;
    int v = (i < NN) ? g_cnt[i] : 0;
    int x = v;
    #pragma unroll
    for (int o = 1; o < 32; o <<= 1) {
        int t = __shfl_up_sync(0xffffffffu, x, o);
        if (lane >= o) x += t;
    }
    if (lane == 31) ws[wid] = x;
    __syncthreads();
    if (wid == 0) {
        int t = ws[lane];
        #pragma unroll
        for (int o = 1; o < 32; o <<= 1) {
            int u = __shfl_up_sync(0xffffffffu, t, o);
            if (lane >= o) t += u;
        }
        ws[lane] = t;
    }
    __syncthreads();
    int excl = x - v + (wid ? ws[wid - 1] : 0);
    if (i < NN) {
        g_rowptr[i] = excl;
        g_invdeg[i] = 1.0f / (float)max(v, 1);
        g_cnt[i] = 0;     // ready for next replay's histogram
        g_cur[i] = 0;     // scatter cursor
    }
    if (tid == 1023) {
        g_bsum[blockIdx.x] = excl + v;
        __threadfence();
        is_last = (atomicAdd(&g_scan_done, 1) == 48);
    }
    __syncthreads();
    if (is_last && tid < 32) {
        __threadfence();   // acquire other blocks' g_bsum writes
        int carry = 0;
        #pragma unroll
        for (int base = 0; base < 64; base += 32) {
            int idx = base + tid;
            int bv = (idx < 49) ? g_bsum[idx] : 0;
            int bx = bv;
            #pragma unroll
            for (int o = 1; o < 32; o <<= 1) {
                int t = __shfl_up_sync(0xffffffffu, bx, o);
                if (tid >= o) bx += t;
            }
            int tot = __shfl_sync(0xffffffffu, bx, 31);
            if (idx < 49) g_bsum[idx] = carry + bx - bv;   // exclusive prefix
            if (idx == 48) g_rowptr[NN] = bv;
            carry += tot;
        }
        if (tid == 0) g_scan_done = 0;   // ready for next replay
    }
}

__global__ void k_scatter(const int* __restrict__ src, const int* __restrict__ dst,
                          const float* __restrict__ ea) {
    trig();   // let conv1 GEMM launch + run concurrently (it only reads x/wc1)
    gds();
    int e = blockIdx.x * 256 + threadIdx.x;
    if (e < NE) {
        int d = dst[e];
        int pos = rp(d) + atomicAdd(&g_cur[d], 1);
        g_edge[pos] = make_int2(src[e], __float_as_int(ea[e]));
    }
}

// ---------------- bf16 GEMM (m16n8k16) ----------------
__device__ __forceinline__ void mma16(float* c, unsigned a0, unsigned a1, unsigned a2,
                                      unsigned a3, unsigned b0, unsigned b1) {
    asm volatile(
        "mma.sync.aligned.m16n8k16.row.col.f32.bf16.bf16.f32 "
        "{%0,%1,%2,%3},{%4,%5,%6,%7},{%8,%9},{%0,%1,%2,%3};"
        : "+f"(c[0]), "+f"(c[1]), "+f"(c[2]), "+f"(c[3])
        : "r"(a0), "r"(a1), "r"(a2), "r"(a3), "r"(b0), "r"(b1));
}

constexpr int M_CONV1 = 0, M_PLAIN = 1, M_K1 = 2, M_K2 = 3, M_K3 = 4, M_K4 = 5;

template <int MODE>
__device__ __forceinline__ void epi_row(int gm, int gc, float v0, float v1,
                                        const float* __restrict__ bias) {
    if (gm >= NN) return;
    if constexpr (MODE == M_CONV1) {
        if (gc < 128) g_uv1[(size_t)gm * 64 + (gc >> 1)] = pk(v0, v1);
        else { g_r1[(size_t)gm * 64 + gc - 128] = v0; g_r1[(size_t)gm * 64 + gc - 127] = v1; }
    } else if constexpr (MODE == M_PLAIN) {
        g_a16[(size_t)gm * 32 + (gc >> 1)] = pk(v0 + bias[gc], v1 + bias[gc + 1]);
    } else if constexpr (MODE == M_K1) {
        size_t ix = (size_t)gm * 64 + gc;
        float k0 = v0 + bias[gc], k1 = v1 + bias[gc + 1];
        float h0 = g_hf[ix], h1 = g_hf[ix + 1];
        g_y16[(size_t)gm * 32 + (gc >> 1)] = pk(h0 + 1.5f * k0, h1 + 1.5f * k1);
        g_accf[ix] = h0 + 0.5f * k0; g_accf[ix + 1] = h1 + 0.5f * k1;
    } else if constexpr (MODE == M_K2) {
        size_t ix = (size_t)gm * 64 + gc;
        float k0 = v0 + bias[gc], k1 = v1 + bias[gc + 1];
        float h0 = g_hf[ix], h1 = g_hf[ix + 1];
        g_y16[(size_t)gm * 32 + (gc >> 1)] = pk(h0 + 1.5f * k0, h1 + 1.5f * k1);
        g_accf[ix] += k0; g_accf[ix + 1] += k1;
    } else if constexpr (MODE == M_K3) {
        size_t ix = (size_t)gm * 64 + gc;
        float k0 = v0 + bias[gc], k1 = v1 + bias[gc + 1];
        float h0 = g_hf[ix], h1 = g_hf[ix + 1];
        g_y16[(size_t)gm * 32 + (gc >> 1)] = pk(h0 + 3.0f * k0, h1 + 3.0f * k1);
        g_accf[ix] += k0; g_accf[ix + 1] += k1;
    }
}

// conv1 GEMM (no trig -> secondary launches only at full completion;
// trailing gds joins scatter so completion implies the whole CSR build)
template <int K, int NOUT, int BN, int MODE>
__global__ __launch_bounds__(256)
void gemm16(const float* __restrict__ xin, const float* __restrict__ bias) {
    constexpr int NF = BN / 16;
    __shared__ __align__(16) unsigned As[128][36];
    __shared__ unsigned Bs[32][72];

    const unsigned* Wp = g_wc1;

    const int tid = threadIdx.x;
    const int m0 = blockIdx.x * 128;
    const int n0 = blockIdx.y * BN;
    const int wid = tid >> 5, lane = tid & 31;
    const int wm = (wid & 3) * 32;
    const int wn = (wid >> 2) * (BN / 2);
    const int g = lane >> 2, t = lane & 3;

    float acc[2][NF][4];
    #pragma unroll
    for (int i = 0; i < 2; i++)
        #pragma unroll
        for (int j = 0; j < NF; j++)
            #pragma unroll
            for (int e = 0; e < 4; e++) acc[i][j][e] = 0.f;

    for (int kc = 0; kc < K; kc += 64) {
        __syncthreads();
        #pragma unroll
        for (int i = 0; i < 8; i++) {
            int q = tid + i * 256;
            int row = q >> 4, f4 = q & 15;
            int gm = m0 + row;
            float4 v = make_float4(0.f, 0.f, 0.f, 0.f);
            if (gm < NN)
                v = *reinterpret_cast<const float4*>(xin + (size_t)gm * 256 + kc + f4 * 4);
            As[row][f4 * 2]     = pk(v.x, v.y);
            As[row][f4 * 2 + 1] = pk(v.z, v.w);
        }
        constexpr int BITER = (32 * BN) / 256;
        #pragma unroll
        for (int i = 0; i < BITER; i++) {
            int q = tid + i * 256;
            int r = q / BN, n = q % BN;
            Bs[r][n] = Wp[(size_t)(kc / 2 + r) * NOUT + n0 + n];
        }
        __syncthreads();
        #pragma unroll
        for (int ks = 0; ks < 4; ks++) {
            const int kb = ks * 8;
            unsigned a[2][4];
            #pragma unroll
            for (int mf = 0; mf < 2; mf++) {
                a[mf][0] = As[wm + mf * 16 + g    ][kb + t];
                a[mf][1] = As[wm + mf * 16 + g + 8][kb + t];
                a[mf][2] = As[wm + mf * 16 + g    ][kb + 4 + t];
                a[mf][3] = As[wm + mf * 16 + g + 8][kb + 4 + t];
            }
            unsigned b[NF][2];
            #pragma unroll
            for (int nf = 0; nf < NF; nf++) {
                b[nf][0] = Bs[kb + t    ][wn + nf * 8 + g];
                b[nf][1] = Bs[kb + 4 + t][wn + nf * 8 + g];
            }
            #pragma unroll
            for (int mf = 0; mf < 2; mf++)
                #pragma unroll
                for (int nf = 0; nf < NF; nf++)
                    mma16(acc[mf][nf], a[mf][0], a[mf][1], a[mf][2], a[mf][3],
                          b[nf][0], b[nf][1]);
        }
    }

    #pragma unroll
    for (int mf = 0; mf < 2; mf++)
        #pragma unroll
        for (int nf = 0; nf < NF; nf++) {
            int gm0 = m0 + wm + mf * 16 + g;
            int gc  = n0 + wn + nf * 8 + t * 2;
            epi_row<MODE>(gm0,     gc, acc[mf][nf][0], acc[mf][nf][1], bias);
            epi_row<MODE>(gm0 + 8, gc, acc[mf][nf][2], acc[mf][nf][3], bias);
        }
    gds();   // join with scatter: completion implies both
}

// ---------------- hidden GEMM: weight preload + per-chunk spin-wait --------------
// PHASE = how many agg_pre passes (each adding chunk_expect per chunk) must have
// signaled before this GEMM's chunk data (g_acat rows) is complete.
// MODE == M_K4 additionally runs the fused conv2 GEMM on the fresh h_new tile.
template <int MODE, int WSEL, int YSEL, int PHASE>
__global__ __launch_bounds__(256)
void gemm_h(const float* __restrict__ bias) {
    trig();
    __shared__ __align__(16) unsigned As[128][36];
    __shared__ unsigned Bs[96][72];
    const unsigned* Wp = (WSEL == 1) ? g_wcA : g_wcB;
    const int tid = threadIdx.x;
    // preamble: full 96x64 weight matrix to smem (stable — k_prep completed
    // before conv1 completed, which gated everything downstream)
    #pragma unroll
    for (int i = 0; i < 24; i++) {
        int q = tid + i * 256;
        Bs[q >> 6][q & 63] = Wp[q];
    }
    // spin-wait: this block's 128 nodes aggregated? (replaces grid-wide gds)
    {
        const int c = blockIdx.x;
        if (tid == 0) {
            const int target = PHASE * chunk_expect(c);
            while (*(volatile int*)&g_done[c] < target) __nanosleep(64);
            __threadfence();   // pair with producers' release fences
        }
        __syncthreads();
    }
    const unsigned* __restrict__ y = (YSEL == 0) ? g_h16 : (YSEL == 1) ? g_a16 : g_y16;
    const int m0 = blockIdx.x * 128;
    const int wid = tid >> 5, lane = tid & 31;
    const int wm = (wid & 3) * 32, wn = (wid >> 2) * 32;
    const int g = lane >> 2, t = lane & 3;

    float acc[2][4][4];
    #pragma unroll
    for (int i = 0; i < 2; i++)
        #pragma unroll
        for (int j = 0; j < 4; j++)
            #pragma unroll
            for (int e = 0; e < 4; e++) acc[i][j][e] = 0.f;

    #pragma unroll
    for (int chunk = 0; chunk < 3; chunk++) {
        __syncthreads();
        #pragma unroll
        for (int i = 0; i < 4; i++) {
            int q = tid + i * 256;
            int row = q >> 3, q4 = q & 7;
            int gm = m0 + row;
            uint4 v = make_uint4(0, 0, 0, 0);
            if (gm < NN) {
                const unsigned* p = (chunk == 0) ? g_acat + (size_t)gm * 64 + q4 * 4
                                  : (chunk == 1) ? g_acat + (size_t)gm * 64 + 32 + q4 * 4
                                  :                y + (size_t)gm * 32 + q4 * 4;
                v = *reinterpret_cast<const uint4*>(p);
            }
            *reinterpret_cast<uint4*>(&As[row][q4 * 4]) = v;
        }
        __syncthreads();
        const int c32 = chunk * 32;
        #pragma unroll
        for (int ks = 0; ks < 4; ks++) {
            const int kb = ks * 8;
            unsigned a[2][4];
            #pragma unroll
            for (int mf = 0; mf < 2; mf++) {
                a[mf][0] = As[wm + mf * 16 + g    ][kb + t];
                a[mf][1] = As[wm + mf * 16 + g + 8][kb + t];
                a[mf][2] = As[wm + mf * 16 + g    ][kb + 4 + t];
                a[mf][3] = As[wm + mf * 16 + g + 8][kb + 4 + t];
            }
            unsigned b[4][2];
            #pragma unroll
            for (int nf = 0; nf < 4; nf++) {
                b[nf][0] = Bs[c32 + kb + t    ][wn + nf * 8 + g];
                b[nf][1] = Bs[c32 + kb + 4 + t][wn + nf * 8 + g];
            }
            #pragma unroll
            for (int mf = 0; mf < 2; mf++)
                #pragma unroll
                for (int nf = 0; nf < 4; nf++)
                    mma16(acc[mf][nf], a[mf][0], a[mf][1], a[mf][2], a[mf][3],
                          b[nf][0], b[nf][1]);
        }
    }

    if constexpr (MODE != M_K4) {
        #pragma unroll
        for (int mf = 0; mf < 2; mf++)
            #pragma unroll
            for (int nf = 0; nf < 4; nf++) {
                int gm0 = m0 + wm + mf * 16 + g;
                int gc  = wn + nf * 8 + t * 2;
                epi_row<MODE>(gm0,     gc, acc[mf][nf][0], acc[mf][nf][1], bias);
                epi_row<MODE>(gm0 + 8, gc, acc[mf][nf][2], acc[mf][nf][3], bias);
            }
    } else {
        // ---- fused: h_new into As (bf16), then conv2 GEMM (K=64, N=48) ----
        __syncthreads();   // all mma reads of As/Bs done
        #pragma unroll
        for (int mf = 0; mf < 2; mf++)
            #pragma unroll
            for (int nf = 0; nf < 4; nf++) {
                #pragma unroll
                for (int half = 0; half < 2; half++) {
                    int row = wm + mf * 16 + g + half * 8;
                    int gm  = m0 + row;
                    int gc  = wn + nf * 8 + t * 2;
                    float hn0 = 0.f, hn1 = 0.f;
                    if (gm < NN) {
                        size_t ix = (size_t)gm * 64 + gc;
                        float k0 = acc[mf][nf][half * 2]     + bias[gc];
                        float k1 = acc[mf][nf][half * 2 + 1] + bias[gc + 1];
                        hn0 = g_accf[ix]     + 0.5f * k0;
                        hn1 = g_accf[ix + 1] + 0.5f * k1;
                    }
                    As[row][gc >> 1] = pk(hn0, hn1);
                }
            }
        #pragma unroll
        for (int i = 0; i < 6; i++) {
            int q = tid + i * 256;
            Bs[q / 48][q % 48] = g_wc2[q];
        }
        __syncthreads();

        const int wn2 = (wid >> 2) * 24;
        float a2[2][3][4];
        #pragma unroll
        for (int i = 0; i < 2; i++)
            #pragma unroll
            for (int j = 0; j < 3; j++)
                #pragma unroll
                for (int e = 0; e < 4; e++) a2[i][j][e] = 0.f;

        #pragma unroll
        for (int ks = 0; ks < 4; ks++) {
            const int kb = ks * 8;
            unsigned a[2][4];
            #pragma unroll
            for (int mf = 0; mf < 2; mf++) {
                a[mf][0] = As[wm + mf * 16 + g    ][kb + t];
                a[mf][1] = As[wm + mf * 16 + g + 8][kb + t];
                a[mf][2] = As[wm + mf * 16 + g    ][kb + 4 + t];
                a[mf][3] = As[wm + mf * 16 + g + 8][kb + 4 + t];
            }
            unsigned b[3][2];
            #pragma unroll
            for (int nf = 0; nf < 3; nf++) {
                b[nf][0] = Bs[kb + t    ][wn2 + nf * 8 + g];
                b[nf][1] = Bs[kb + 4 + t][wn2 + nf * 8 + g];
            }
            #pragma unroll
            for (int mf = 0; mf < 2; mf++)
                #pragma unroll
                for (int nf = 0; nf < 3; nf++)
                    mma16(a2[mf][nf], a[mf][0], a[mf][1], a[mf][2], a[mf][3],
                          b[nf][0], b[nf][1]);
        }

        #pragma unroll
        for (int mf = 0; mf < 2; mf++)
            #pragma unroll
            for (int nf = 0; nf < 3; nf++) {
                #pragma unroll
                for (int half = 0; half < 2; half++) {
                    int gm = m0 + wm + mf * 16 + g + half * 8;
                    int gc = wn2 + nf * 8 + t * 2;
                    if (gm >= NN) continue;
                    float v0 = a2[mf][nf][half * 2], v1 = a2[mf][nf][half * 2 + 1];
                    if (gc < 32) g_uv2[(size_t)gm * 16 + (gc >> 1)] = pk(v0, v1);
                    else { g_r2[(size_t)gm * 16 + gc - 32] = v0;
                           g_r2[(size_t)gm * 16 + gc - 31] = v1; }
                }
            }
    }
}

// ---------------- aggregation: warp per node, 4 edges/iter via 8-lane groups ------
__global__ __launch_bounds__(256)
void agg_post1(const float* __restrict__ b1) {
    trig();
    int node = (blockIdx.x << 3) + (threadIdx.x >> 5);
    int lane = threadIdx.x & 31;
    int lane8 = lane & 7, grp = lane >> 3;
    int beg = rp(node), end = rp(node + 1);
    float id = g_invdeg[node];
    gds();
    float m[8];
    #pragma unroll
    for (int j = 0; j < 8; j++) m[j] = 0.f;

    auto body = [&](int e) {
        int2 E = g_edge[e];
        float p = __int_as_float(E.y), q = 1.f - p;
        const unsigned* row = g_uv1 + (size_t)E.x * 64 + lane8 * 4;
        uint4 U = *reinterpret_cast<const uint4*>(row);
        uint4 V = *reinterpret_cast<const uint4*>(row + 32);
        float2 u0 = up(U.x), u1 = up(U.y), u2 = up(U.z), u3 = up(U.w);
        float2 v0 = up(V.x), v1 = up(V.y), v2 = up(V.z), v3 = up(V.w);
        m[0] += q * u0.x + p * v0.x;  m[1] += q * u0.y + p * v0.y;
        m[2] += q * u1.x + p * v1.x;  m[3] += q * u1.y + p * v1.y;
        m[4] += q * u2.x + p * v2.x;  m[5] += q * u2.y + p * v2.y;
        m[6] += q * u3.x + p * v3.x;  m[7] += q * u3.y + p * v3.y;
    };

    int e = beg;
    for (; e + 8 <= end; e += 8) { body(e + grp); body(e + 4 + grp); }
    for (; e + 4 <= end; e += 4) body(e + grp);
    if (e + grp < end) body(e + grp);

    #pragma unroll
    for (int o = 8; o <= 16; o <<= 1)
        #pragma unroll
        for (int j = 0; j < 8; j++)
            m[j] += __shfl_xor_sync(0xffffffffu, m[j], o);

    if (grp == 0) {
        size_t ix = (size_t)node * 64 + lane8 * 8;
        float4 r0 = *reinterpret_cast<const float4*>(g_r1 + ix);
        float4 r1 = *reinterpret_cast<const float4*>(g_r1 + ix + 4);
        float h[8];
        #pragma unroll
        for (int j = 0; j < 8; j++) {
            float r = (j < 4) ? (&r0.x)[j] : (&r1.x)[j - 4];
            h[j] = tanhf(m[j] * id + r + b1[lane8 * 8 + j]);
        }
        *reinterpret_cast<float4*>(g_hf + ix)     = make_float4(h[0], h[1], h[2], h[3]);
        *reinterpret_cast<float4*>(g_hf + ix + 4) = make_float4(h[4], h[5], h[6], h[7]);
        uint4 o16 = make_uint4(pk(h[0], h[1]), pk(h[2], h[3]), pk(h[4], h[5]), pk(h[6], h[7]));
        *reinterpret_cast<uint4*>(g_h16 + (size_t)node * 32 + lane8 * 4) = o16;
    }
}

// hidden pre-agg: writes acat then signals its 128-node chunk counter.
template <int YSEL>  // 0=g_h16, 1=g_a16, 2=g_y16
__global__ __launch_bounds__(256)
void agg_pre() {
    trig();
    int node = (blockIdx.x << 3) + (threadIdx.x >> 5);
    int lane = threadIdx.x & 31;
    int lane8 = lane & 7, grp = lane >> 3;
    int beg = rp(node), end = rp(node + 1);
    float id = g_invdeg[node];
    gds();
    const unsigned* __restrict__ y = (YSEL == 0) ? g_h16 : (YSEL == 1) ? g_a16 : g_y16;
    float a0[8], a1[8];
    #pragma unroll
    for (int j = 0; j < 8; j++) { a0[j] = 0.f; a1[j] = 0.f; }

    auto body = [&](int e) {
        int2 E = g_edge[e];
        float p = __int_as_float(E.y), q = 1.f - p;
        uint4 v = *reinterpret_cast<const uint4*>(y + (size_t)E.x * 32 + lane8 * 4);
        float2 f0 = up(v.x), f1 = up(v.y), f2 = up(v.z), f3 = up(v.w);
        a0[0] += q * f0.x;  a0[1] += q * f0.y;  a0[2] += q * f1.x;  a0[3] += q * f1.y;
        a0[4] += q * f2.x;  a0[5] += q * f2.y;  a0[6] += q * f3.x;  a0[7] += q * f3.y;
        a1[0] += p * f0.x;  a1[1] += p * f0.y;  a1[2] += p * f1.x;  a1[3] += p * f1.y;
        a1[4] += p * f2.x;  a1[5] += p * f2.y;  a1[6] += p * f3.x;  a1[7] += p * f3.y;
    };

    int e = beg;
    for (; e + 8 <= end; e += 8) { body(e + grp); body(e + 4 + grp); }
    for (; e + 4 <= end; e += 4) body(e + grp);
    if (e + grp < end) body(e + grp);

    #pragma unroll
    for (int o = 8; o <= 16; o <<= 1)
        #pragma unroll
        for (int j = 0; j < 8; j++) {
            a0[j] += __shfl_xor_sync(0xffffffffu, a0[j], o);
            a1[j] += __shfl_xor_sync(0xffffffffu, a1[j], o);
        }

    if (grp == 0) {
        uint4 o0 = make_uint4(pk(a0[0] * id, a0[1] * id), pk(a0[2] * id, a0[3] * id),
                              pk(a0[4] * id, a0[5] * id), pk(a0[6] * id, a0[7] * id));
        uint4 o1 = make_uint4(pk(a1[0] * id, a1[1] * id), pk(a1[2] * id, a1[3] * id),
                              pk(a1[4] * id, a1[5] * id), pk(a1[6] * id, a1[7] * id));
        *reinterpret_cast<uint4*>(g_acat + (size_t)node * 64 + lane8 * 4)      = o0;
        *reinterpret_cast<uint4*>(g_acat + (size_t)node * 64 + 32 + lane8 * 4) = o1;
    }
    // release-signal this block's chunk (CUB decoupled-lookback pattern)
    __syncthreads();
    if (threadIdx.x == 0) {
        __threadfence();
        atomicAdd(&g_done[blockIdx.x >> 4], 1);
    }
}

// conv2: gather + tanh + log_softmax(16); 16 threads per node
__global__ __launch_bounds__(256)
void conv2_fin(const float* __restrict__ b2, float* __restrict__ out) {
    trig();
    int node = blockIdx.x * 16 + (threadIdx.x >> 4);
    int c = threadIdx.x & 15;
    int beg = rp(node), end = rp(node + 1);
    float id = g_invdeg[node];
    gds();
    float m = 0.f;
    int e = beg;
    for (; e + 2 <= end; e += 2) {
        int2 E0 = g_edge[e], E1 = g_edge[e + 1];
        float p0 = __int_as_float(E0.y), p1 = __int_as_float(E1.y);
        float u0 = bfh(g_uv2[(size_t)E0.x * 16 + (c >> 1)], c & 1);
        float v0 = bfh(g_uv2[(size_t)E0.x * 16 + 8 + (c >> 1)], c & 1);
        float u1 = bfh(g_uv2[(size_t)E1.x * 16 + (c >> 1)], c & 1);
        float v1 = bfh(g_uv2[(size_t)E1.x * 16 + 8 + (c >> 1)], c & 1);
        m += (1.f - p0) * u0 + p0 * v0 + (1.f - p1) * u1 + p1 * v1;
    }
    if (e < end) {
        int2 E0 = g_edge[e];
        float p0 = __int_as_float(E0.y);
        float u = bfh(g_uv2[(size_t)E0.x * 16 + (c >> 1)], c & 1);
        float v = bfh(g_uv2[(size_t)E0.x * 16 + 8 + (c >> 1)], c & 1);
        m += (1.f - p0) * u + p0 * v;
    }
    float o = tanhf(m * id + g_r2[(size_t)node * 16 + c] + b2[c]);
    float mx = o;
    #pragma unroll
    for (int k = 8; k; k >>= 1) mx = fmaxf(mx, __shfl_xor_sync(0xffffffffu, mx, k));
    float s = expf(o - mx);
    float tot = s;
    #pragma unroll
    for (int k = 8; k; k >>= 1) tot += __shfl_xor_sync(0xffffffffu, tot, k);
    out[(size_t)node * 16 + c] = o - mx - logf(tot);
}

// ---------------- launch helpers (PDL on every kernel) ----------------
template <typename F, typename... Args>
static inline void pdl(F f, dim3 grid, dim3 block, Args... args) {
    cudaLaunchConfig_t cfg = {};
    cfg.gridDim = grid;
    cfg.blockDim = block;
    cfg.dynamicSmemBytes = 0;
    cfg.stream = 0;
    cudaLaunchAttribute a[1];
    a[0].id = cudaLaunchAttributeProgrammaticStreamSerialization;
    a[0].val.programmaticStreamSerializationAllowed = 1;
    cfg.attrs = a;
    cfg.numAttrs = 1;
    cudaLaunchKernelEx(&cfg, f, args...);
}

extern "C" void kernel_launch(void* const* d_in, const int* in_sizes, int n_in,
                              void* d_out, int out_size) {
    const float* x   = (const float*)d_in[0];
    const float* ea  = (const float*)d_in[1];
    const int*   src = (const int*)  d_in[2];
    const int*   dst = (const int*)  d_in[3];
    const float* W1  = (const float*)d_in[4];
    const float* R1  = (const float*)d_in[5];
    const float* b1  = (const float*)d_in[6];
    const float* Wa  = (const float*)d_in[7];
    const float* Ra  = (const float*)d_in[8];
    const float* ba  = (const float*)d_in[9];
    const float* Wb  = (const float*)d_in[10];
    const float* Rb  = (const float*)d_in[11];
    const float* bb  = (const float*)d_in[12];
    const float* W2  = (const float*)d_in[13];
    const float* R2  = (const float*)d_in[14];
    const float* b2  = (const float*)d_in[15];
    float* out = (float*)d_out;

    // CSR build + weight prep (hist and pack merged; cnt/cur zeroed by scan)
    pdl(k_prep, dim3(932), dim3(256), dst, W1, R1, Wa, Ra, Wb, Rb, W2, R2);
    pdl(k_scan, dim3(49), dim3(1024));
    pdl(k_scatter, dim3(3125), dim3(256), src, dst, ea);

    dim3 g1(391, 3), gh(391, 1), ga(6250), gb(256);

    // conv1 GEMM: overlaps scatter (no leading gds); trailing gds joins scatter
    pdl(gemm16<256, 192, 64, M_CONV1>, g1, gb, x, (const float*)nullptr);
    pdl(agg_post1, ga, gb, b1);

    // RK4: 8 (agg_pre + gemm_h) pairs; gemm_h uses per-chunk spin instead of gds
    pdl(agg_pre<0>, ga, gb);
    pdl(gemm_h<M_PLAIN, 1, 0, 1>, gh, gb, ba);
    pdl(agg_pre<1>, ga, gb);
    pdl(gemm_h<M_K1,    2, 1, 2>, gh, gb, bb);

    pdl(agg_pre<2>, ga, gb);
    pdl(gemm_h<M_PLAIN, 1, 2, 3>, gh, gb, ba);
    pdl(agg_pre<1>, ga, gb);
    pdl(gemm_h<M_K2,    2, 1, 4>, gh, gb, bb);

    pdl(agg_pre<2>, ga, gb);
    pdl(gemm_h<M_PLAIN, 1, 2, 5>, gh, gb, ba);
    pdl(agg_pre<1>, ga, gb);
    pdl(gemm_h<M_K3,    2, 1, 6>, gh, gb, bb);

    pdl(agg_pre<2>, ga, gb);
    pdl(gemm_h<M_PLAIN, 1, 2, 7>, gh, gb, ba);
    pdl(agg_pre<1>, ga, gb);
    pdl(gemm_h<M_K4,    2, 1, 8>, gh, gb, bb);   // + fused conv2 GEMM

    // finish
    pdl(conv2_fin, dim3(3125), gb, b2, out);
}

// round 10
// speedup vs baseline: 1.1098x; 1.1098x over previous
#include <cuda_runtime.h>
#include <cuda_bf16.h>
#include <cstdint>
#include <cstddef>

#define NN 50000
#define NE 800000

// ---------------- static device scratch ----------------
__device__ int   g_cnt[NN];          // histogram (re-zeroed by k_scan each run)
__device__ int   g_cur[NN];          // scatter cursor (re-zeroed by k_scan)
__device__ int   g_rowptr[NN + 1];
__device__ int   g_bsum[64];
__device__ int   g_scan_done;
__device__ __align__(16) int2 g_edge[NE];   // (src, float bits of p)
__device__ float g_invdeg[NN];

// bf16x2-packed tables (u32 each = 2 features)
__device__ __align__(16) unsigned g_x16 [(size_t)NN * 128]; // x pre-packed bf16
__device__ __align__(16) unsigned g_uv1 [(size_t)NN * 64];  // conv1 u|v (128 feats)
__device__ __align__(16) unsigned g_h16 [(size_t)NN * 32];
__device__ __align__(16) unsigned g_a16 [(size_t)NN * 32];
__device__ __align__(16) unsigned g_y16 [(size_t)NN * 32];
__device__ __align__(16) unsigned g_acat[(size_t)NN * 64];  // A0|A1 (128 feats)
__device__ __align__(16) unsigned g_uv2 [(size_t)NN * 16];  // conv2 u|v (32 feats)

// fp32 state
__device__ __align__(16) float g_r1  [(size_t)NN * 64];
__device__ __align__(16) float g_hf  [(size_t)NN * 64];
__device__ __align__(16) float g_accf[(size_t)NN * 64];
__device__ __align__(16) float g_r2  [(size_t)NN * 16];

// packed weights
__device__ unsigned g_wc1[128 * 192];
__device__ unsigned g_wcA[96 * 64];
__device__ unsigned g_wcB[96 * 64];
__device__ unsigned g_wc2[32 * 48];

// ---------------- helpers ----------------
__device__ __forceinline__ void gds() {
#if __CUDA_ARCH__ >= 900
    cudaGridDependencySynchronize();
#endif
}
__device__ __forceinline__ void trig() {
#if __CUDA_ARCH__ >= 900
    cudaTriggerProgrammaticLaunchCompletion();
#endif
}
__device__ __forceinline__ unsigned pk(float a, float b) {
    __nv_bfloat162 h = __floats2bfloat162_rn(a, b);
    return *reinterpret_cast<unsigned*>(&h);
}
__device__ __forceinline__ float2 up(unsigned u) {
    __nv_bfloat162 h = *reinterpret_cast<__nv_bfloat162*>(&u);
    return make_float2(__bfloat162float(h.x), __bfloat162float(h.y));
}
__device__ __forceinline__ float bfh(unsigned u, int hi) {
    unsigned short s = hi ? (unsigned short)(u >> 16) : (unsigned short)(u & 0xffff);
    __nv_bfloat16 b = *reinterpret_cast<__nv_bfloat16*>(&s);
    return __bfloat162float(b);
}
__device__ __forceinline__ int rp(int i) {
    return g_rowptr[i] + g_bsum[i >> 10];
}

// ---------------- prep: edge histogram + weight pack + x bf16 pack ----------------
// NO trig: k_scan (and transitively scatter/conv1) launch only after full
// completion, making conv1's pre-gds reads of g_wc1/g_x16 safe.
__global__ void k_prep(const int* __restrict__ dst, const float* __restrict__ x,
                       const float* __restrict__ W1, const float* __restrict__ R1,
                       const float* __restrict__ Wa, const float* __restrict__ Ra,
                       const float* __restrict__ Wb, const float* __restrict__ Rb,
                       const float* __restrict__ W2, const float* __restrict__ R2) {
    gds();
    if (blockIdx.x < 782) {                       // histogram: 4 edges per thread
        int q = blockIdx.x * 256 + threadIdx.x;
        if (q * 4 < NE) {
            int4 d = *reinterpret_cast<const int4*>(dst + q * 4);
            atomicAdd(&g_cnt[d.x], 1);
            atomicAdd(&g_cnt[d.y], 1);
            atomicAdd(&g_cnt[d.z], 1);
            atomicAdd(&g_cnt[d.w], 1);
        }
        return;
    }
    if (blockIdx.x >= 932) {                      // x -> bf16 pack: 8 u32 per thread
        size_t j = (size_t)(blockIdx.x - 932) * 256 + threadIdx.x;
        size_t ob = j * 8;                         // 800000 threads * 8 = NN*128
        const float4* xp = reinterpret_cast<const float4*>(x + ob * 2);
        float4 v0 = xp[0], v1 = xp[1], v2 = xp[2], v3 = xp[3];
        uint4 o0 = make_uint4(pk(v0.x, v0.y), pk(v0.z, v0.w),
                              pk(v1.x, v1.y), pk(v1.z, v1.w));
        uint4 o1 = make_uint4(pk(v2.x, v2.y), pk(v2.z, v2.w),
                              pk(v3.x, v3.y), pk(v3.z, v3.w));
        reinterpret_cast<uint4*>(g_x16 + ob)[0] = o0;
        reinterpret_cast<uint4*>(g_x16 + ob)[1] = o1;
        return;
    }
    int i = (blockIdx.x - 782) * 256 + threadIdx.x;
    if (i < 24576) {                        // g_wc1 [128][192], K=256
        int k2 = i / 192, c = i % 192;
        int ke = 2 * k2, ko = ke + 1;
        float e, o;
        if (c < 64)       { e = W1[ke * 64 + c];              o = W1[ko * 64 + c]; }
        else if (c < 128) { e = W1[(256 + ke) * 64 + c - 64];  o = W1[(256 + ko) * 64 + c - 64]; }
        else              { e = R1[ke * 64 + c - 128];         o = R1[ko * 64 + c - 128]; }
        g_wc1[i] = pk(e, o);
    } else if (i < 30720) {                 // g_wcA [96][64], K=192
        int j = i - 24576, k2 = j / 64, c = j % 64;
        int ke = 2 * k2, ko = ke + 1;
        float e = (ke < 128) ? Wa[ke * 64 + c] : Ra[(ke - 128) * 64 + c];
        float o = (ko < 128) ? Wa[ko * 64 + c] : Ra[(ko - 128) * 64 + c];
        g_wcA[j] = pk(e, o);
    } else if (i < 36864) {                 // g_wcB
        int j = i - 30720, k2 = j / 64, c = j % 64;
        int ke = 2 * k2, ko = ke + 1;
        float e = (ke < 128) ? Wb[ke * 64 + c] : Rb[(ke - 128) * 64 + c];
        float o = (ko < 128) ? Wb[ko * 64 + c] : Rb[(ko - 128) * 64 + c];
        g_wcB[j] = pk(e, o);
    } else if (i < 38400) {                 // g_wc2 [32][48], K=64
        int j = i - 36864, k2 = j / 48, c = j % 48;
        int ke = 2 * k2, ko = ke + 1;
        float e, o;
        if (c < 16)      { e = W2[ke * 16 + c];              o = W2[ko * 16 + c]; }
        else if (c < 32) { e = W2[(64 + ke) * 16 + c - 16];  o = W2[(64 + ko) * 16 + c - 16]; }
        else             { e = R2[ke * 16 + c - 32];         o = R2[ko * 16 + c - 32]; }
        g_wc2[j] = pk(e, o);
    }
}

// block-local exclusive scan; zero cnt/cur; LAST-finishing block's warp 0 does
// the cross-block scan and resets g_scan_done. NO trig (see k_prep comment).
__global__ void k_scan() {
    gds();
    __shared__ int ws[32];
    __shared__ int is_last;
    int tid = threadIdx.x, lane = tid & 31, wid = tid >> 5;
    int i = blockIdx.x * 1024 + tid;
    int v = (i < NN) ? g_cnt[i] : 0;
    int x = v;
    #pragma unroll
    for (int o = 1; o < 32; o <<= 1) {
        int t = __shfl_up_sync(0xffffffffu, x, o);
        if (lane >= o) x += t;
    }
    if (lane == 31) ws[wid] = x;
    __syncthreads();
    if (wid == 0) {
        int t = ws[lane];
        #pragma unroll
        for (int o = 1; o < 32; o <<= 1) {
            int u = __shfl_up_sync(0xffffffffu, t, o);
            if (lane >= o) t += u;
        }
        ws[lane] = t;
    }
    __syncthreads();
    int excl = x - v + (wid ? ws[wid - 1] : 0);
    if (i < NN) {
        g_rowptr[i] = excl;
        g_invdeg[i] = 1.0f / (float)max(v, 1);
        g_cnt[i] = 0;     // ready for next replay's histogram
        g_cur[i] = 0;     // scatter cursor
    }
    if (tid == 1023) {
        g_bsum[blockIdx.x] = excl + v;
        __threadfence();
        is_last = (atomicAdd(&g_scan_done, 1) == 48);
    }
    __syncthreads();
    if (is_last && tid < 32) {
        __threadfence();   // acquire other blocks' g_bsum writes
        int carry = 0;
        #pragma unroll
        for (int base = 0; base < 64; base += 32) {
            int idx = base + tid;
            int bv = (idx < 49) ? g_bsum[idx] : 0;
            int bx = bv;
            #pragma unroll
            for (int o = 1; o < 32; o <<= 1) {
                int t = __shfl_up_sync(0xffffffffu, bx, o);
                if (tid >= o) bx += t;
            }
            int tot = __shfl_sync(0xffffffffu, bx, 31);
            if (idx < 49) g_bsum[idx] = carry + bx - bv;   // exclusive prefix
            if (idx == 48) g_rowptr[NN] = bv;
            carry += tot;
        }
        if (tid == 0) g_scan_done = 0;   // ready for next replay
    }
}

__global__ void k_scatter(const int* __restrict__ src, const int* __restrict__ dst,
                          const float* __restrict__ ea) {
    trig();   // let conv1 GEMM launch + run concurrently (reads only x16/wc1,
              // both sealed: k_prep completed before k_scan even launched)
    gds();
    int e = blockIdx.x * 256 + threadIdx.x;
    if (e < NE) {
        int d = dst[e];
        int pos = rp(d) + atomicAdd(&g_cur[d], 1);
        g_edge[pos] = make_int2(src[e], __float_as_int(ea[e]));
    }
}

// ---------------- bf16 GEMM (m16n8k16) ----------------
__device__ __forceinline__ void mma16(float* c, unsigned a0, unsigned a1, unsigned a2,
                                      unsigned a3, unsigned b0, unsigned b1) {
    asm volatile(
        "mma.sync.aligned.m16n8k16.row.col.f32.bf16.bf16.f32 "
        "{%0,%1,%2,%3},{%4,%5,%6,%7},{%8,%9},{%0,%1,%2,%3};"
        : "+f"(c[0]), "+f"(c[1]), "+f"(c[2]), "+f"(c[3])
        : "r"(a0), "r"(a1), "r"(a2), "r"(a3), "r"(b0), "r"(b1));
}

constexpr int M_CONV1 = 0, M_PLAIN = 1, M_K1 = 2, M_K2 = 3, M_K3 = 4, M_K4 = 5;

template <int MODE>
__device__ __forceinline__ void epi_row(int gm, int gc, float v0, float v1,
                                        const float* __restrict__ bias) {
    if (gm >= NN) return;
    if constexpr (MODE == M_CONV1) {
        if (gc < 128) g_uv1[(size_t)gm * 64 + (gc >> 1)] = pk(v0, v1);
        else { g_r1[(size_t)gm * 64 + gc - 128] = v0; g_r1[(size_t)gm * 64 + gc - 127] = v1; }
    } else if constexpr (MODE == M_PLAIN) {
        g_a16[(size_t)gm * 32 + (gc >> 1)] = pk(v0 + bias[gc], v1 + bias[gc + 1]);
    } else if constexpr (MODE == M_K1) {
        size_t ix = (size_t)gm * 64 + gc;
        float k0 = v0 + bias[gc], k1 = v1 + bias[gc + 1];
        float h0 = g_hf[ix], h1 = g_hf[ix + 1];
        g_y16[(size_t)gm * 32 + (gc >> 1)] = pk(h0 + 1.5f * k0, h1 + 1.5f * k1);
        g_accf[ix] = h0 + 0.5f * k0; g_accf[ix + 1] = h1 + 0.5f * k1;
    } else if constexpr (MODE == M_K2) {
        size_t ix = (size_t)gm * 64 + gc;
        float k0 = v0 + bias[gc], k1 = v1 + bias[gc + 1];
        float h0 = g_hf[ix], h1 = g_hf[ix + 1];
        g_y16[(size_t)gm * 32 + (gc >> 1)] = pk(h0 + 1.5f * k0, h1 + 1.5f * k1);
        g_accf[ix] += k0; g_accf[ix + 1] += k1;
    } else if constexpr (MODE == M_K3) {
        size_t ix = (size_t)gm * 64 + gc;
        float k0 = v0 + bias[gc], k1 = v1 + bias[gc + 1];
        float h0 = g_hf[ix], h1 = g_hf[ix + 1];
        g_y16[(size_t)gm * 32 + (gc >> 1)] = pk(h0 + 3.0f * k0, h1 + 3.0f * k1);
        g_accf[ix] += k0; g_accf[ix + 1] += k1;
    }
}

// conv1 GEMM reading pre-packed bf16 x; trig at entry (downstream preamble-safe);
// trailing gds joins scatter.
template <int K, int NOUT, int BN, int MODE>
__global__ __launch_bounds__(256)
void gemm16(const float* __restrict__ bias) {
    trig();
    constexpr int NF = BN / 16;
    __shared__ __align__(16) unsigned As[128][36];
    __shared__ unsigned Bs[32][72];

    const unsigned* Wp = g_wc1;

    const int tid = threadIdx.x;
    const int m0 = blockIdx.x * 128;
    const int n0 = blockIdx.y * BN;
    const int wid = tid >> 5, lane = tid & 31;
    const int wm = (wid & 3) * 32;
    const int wn = (wid >> 2) * (BN / 2);
    const int g = lane >> 2, t = lane & 3;

    float acc[2][NF][4];
    #pragma unroll
    for (int i = 0; i < 2; i++)
        #pragma unroll
        for (int j = 0; j < NF; j++)
            #pragma unroll
            for (int e = 0; e < 4; e++) acc[i][j][e] = 0.f;

    for (int kc = 0; kc < K; kc += 64) {
        __syncthreads();
        #pragma unroll
        for (int i = 0; i < 4; i++) {
            int q = tid + i * 256;
            int row = q >> 3, q4 = q & 7;
            int gm = m0 + row;
            uint4 v = make_uint4(0, 0, 0, 0);
            if (gm < NN)
                v = *reinterpret_cast<const uint4*>(
                        g_x16 + (size_t)gm * 128 + kc / 2 + q4 * 4);
            *reinterpret_cast<uint4*>(&As[row][q4 * 4]) = v;
        }
        constexpr int BITER = (32 * BN) / 256;
        #pragma unroll
        for (int i = 0; i < BITER; i++) {
            int q = tid + i * 256;
            int r = q / BN, n = q % BN;
            Bs[r][n] = Wp[(size_t)(kc / 2 + r) * NOUT + n0 + n];
        }
        __syncthreads();
        #pragma unroll
        for (int ks = 0; ks < 4; ks++) {
            const int kb = ks * 8;
            unsigned a[2][4];
            #pragma unroll
            for (int mf = 0; mf < 2; mf++) {
                a[mf][0] = As[wm + mf * 16 + g    ][kb + t];
                a[mf][1] = As[wm + mf * 16 + g + 8][kb + t];
                a[mf][2] = As[wm + mf * 16 + g    ][kb + 4 + t];
                a[mf][3] = As[wm + mf * 16 + g + 8][kb + 4 + t];
            }
            unsigned b[NF][2];
            #pragma unroll
            for (int nf = 0; nf < NF; nf++) {
                b[nf][0] = Bs[kb + t    ][wn + nf * 8 + g];
                b[nf][1] = Bs[kb + 4 + t][wn + nf * 8 + g];
            }
            #pragma unroll
            for (int mf = 0; mf < 2; mf++)
                #pragma unroll
                for (int nf = 0; nf < NF; nf++)
                    mma16(acc[mf][nf], a[mf][0], a[mf][1], a[mf][2], a[mf][3],
                          b[nf][0], b[nf][1]);
        }
    }

    #pragma unroll
    for (int mf = 0; mf < 2; mf++)
        #pragma unroll
        for (int nf = 0; nf < NF; nf++) {
            int gm0 = m0 + wm + mf * 16 + g;
            int gc  = n0 + wn + nf * 8 + t * 2;
            epi_row<MODE>(gm0,     gc, acc[mf][nf][0], acc[mf][nf][1], bias);
            epi_row<MODE>(gm0 + 8, gc, acc[mf][nf][2], acc[mf][nf][3], bias);
        }
    gds();   // join with scatter: completion implies both
}

// ---------------- hidden GEMM: weight preload pre-gds (R8 semantics) -------------
// MODE == M_K4 additionally runs the fused conv2 GEMM on the fresh h_new tile.
template <int MODE, int WSEL, int YSEL>
__global__ __launch_bounds__(256)
void gemm_h(const float* __restrict__ bias) {
    trig();
    __shared__ __align__(16) unsigned As[128][36];
    __shared__ unsigned Bs[96][72];
    const unsigned* Wp = (WSEL == 1) ? g_wcA : g_wcB;
    const int tid = threadIdx.x;
    // preamble: full 96x64 weight matrix to smem (sealed before RK phase)
    #pragma unroll
    for (int i = 0; i < 24; i++) {
        int q = tid + i * 256;
        Bs[q >> 6][q & 63] = Wp[q];
    }
    gds();
    const unsigned* __restrict__ y = (YSEL == 0) ? g_h16 : (YSEL == 1) ? g_a16 : g_y16;
    const int m0 = blockIdx.x * 128;
    const int wid = tid >> 5, lane = tid & 31;
    const int wm = (wid & 3) * 32, wn = (wid >> 2) * 32;
    const int g = lane >> 2, t = lane & 3;

    float acc[2][4][4];
    #pragma unroll
    for (int i = 0; i < 2; i++)
        #pragma unroll
        for (int j = 0; j < 4; j++)
            #pragma unroll
            for (int e = 0; e < 4; e++) acc[i][j][e] = 0.f;

    #pragma unroll
    for (int chunk = 0; chunk < 3; chunk++) {
        __syncthreads();
        #pragma unroll
        for (int i = 0; i < 4; i++) {
            int q = tid + i * 256;
            int row = q >> 3, q4 = q & 7;
            int gm = m0 + row;
            uint4 v = make_uint4(0, 0, 0, 0);
            if (gm < NN) {
                const unsigned* p = (chunk == 0) ? g_acat + (size_t)gm * 64 + q4 * 4
                                  : (chunk == 1) ? g_acat + (size_t)gm * 64 + 32 + q4 * 4
                                  :                y + (size_t)gm * 32 + q4 * 4;
                v = *reinterpret_cast<const uint4*>(p);
            }
            *reinterpret_cast<uint4*>(&As[row][q4 * 4]) = v;
        }
        __syncthreads();
        const int c32 = chunk * 32;
        #pragma unroll
        for (int ks = 0; ks < 4; ks++) {
            const int kb = ks * 8;
            unsigned a[2][4];
            #pragma unroll
            for (int mf = 0; mf < 2; mf++) {
                a[mf][0] = As[wm + mf * 16 + g    ][kb + t];
                a[mf][1] = As[wm + mf * 16 + g + 8][kb + t];
                a[mf][2] = As[wm + mf * 16 + g    ][kb + 4 + t];
                a[mf][3] = As[wm + mf * 16 + g + 8][kb + 4 + t];
            }
            unsigned b[4][2];
            #pragma unroll
            for (int nf = 0; nf < 4; nf++) {
                b[nf][0] = Bs[c32 + kb + t    ][wn + nf * 8 + g];
                b[nf][1] = Bs[c32 + kb + 4 + t][wn + nf * 8 + g];
            }
            #pragma unroll
            for (int mf = 0; mf < 2; mf++)
                #pragma unroll
                for (int nf = 0; nf < 4; nf++)
                    mma16(acc[mf][nf], a[mf][0], a[mf][1], a[mf][2], a[mf][3],
                          b[nf][0], b[nf][1]);
        }
    }

    if constexpr (MODE != M_K4) {
        #pragma unroll
        for (int mf = 0; mf < 2; mf++)
            #pragma unroll
            for (int nf = 0; nf < 4; nf++) {
                int gm0 = m0 + wm + mf * 16 + g;
                int gc  = wn + nf * 8 + t * 2;
                epi_row<MODE>(gm0,     gc, acc[mf][nf][0], acc[mf][nf][1], bias);
                epi_row<MODE>(gm0 + 8, gc, acc[mf][nf][2], acc[mf][nf][3], bias);
            }
    } else {
        // ---- fused: h_new into As (bf16), then conv2 GEMM (K=64, N=48) ----
        __syncthreads();   // all mma reads of As/Bs done
        #pragma unroll
        for (int mf = 0; mf < 2; mf++)
            #pragma unroll
            for (int nf = 0; nf < 4; nf++) {
                #pragma unroll
                for (int half = 0; half < 2; half++) {
                    int row = wm + mf * 16 + g + half * 8;
                    int gm  = m0 + row;
                    int gc  = wn + nf * 8 + t * 2;
                    float hn0 = 0.f, hn1 = 0.f;
                    if (gm < NN) {
                        size_t ix = (size_t)gm * 64 + gc;
                        float k0 = acc[mf][nf][half * 2]     + bias[gc];
                        float k1 = acc[mf][nf][half * 2 + 1] + bias[gc + 1];
                        hn0 = g_accf[ix]     + 0.5f * k0;
                        hn1 = g_accf[ix + 1] + 0.5f * k1;
                    }
                    As[row][gc >> 1] = pk(hn0, hn1);
                }
            }
        #pragma unroll
        for (int i = 0; i < 6; i++) {
            int q = tid + i * 256;
            Bs[q / 48][q % 48] = g_wc2[q];
        }
        __syncthreads();

        const int wn2 = (wid >> 2) * 24;
        float a2[2][3][4];
        #pragma unroll
        for (int i = 0; i < 2; i++)
            #pragma unroll
            for (int j = 0; j < 3; j++)
                #pragma unroll
                for (int e = 0; e < 4; e++) a2[i][j][e] = 0.f;

        #pragma unroll
        for (int ks = 0; ks < 4; ks++) {
            const int kb = ks * 8;
            unsigned a[2][4];
            #pragma unroll
            for (int mf = 0; mf < 2; mf++) {
                a[mf][0] = As[wm + mf * 16 + g    ][kb + t];
                a[mf][1] = As[wm + mf * 16 + g + 8][kb + t];
                a[mf][2] = As[wm + mf * 16 + g    ][kb + 4 + t];
                a[mf][3] = As[wm + mf * 16 + g + 8][kb + 4 + t];
            }
            unsigned b[3][2];
            #pragma unroll
            for (int nf = 0; nf < 3; nf++) {
                b[nf][0] = Bs[kb + t    ][wn2 + nf * 8 + g];
                b[nf][1] = Bs[kb + 4 + t][wn2 + nf * 8 + g];
            }
            #pragma unroll
            for (int mf = 0; mf < 2; mf++)
                #pragma unroll
                for (int nf = 0; nf < 3; nf++)
                    mma16(a2[mf][nf], a[mf][0], a[mf][1], a[mf][2], a[mf][3],
                          b[nf][0], b[nf][1]);
        }

        #pragma unroll
        for (int mf = 0; mf < 2; mf++)
            #pragma unroll
            for (int nf = 0; nf < 3; nf++) {
                #pragma unroll
                for (int half = 0; half < 2; half++) {
                    int gm = m0 + wm + mf * 16 + g + half * 8;
                    int gc = wn2 + nf * 8 + t * 2;
                    if (gm >= NN) continue;
                    float v0 = a2[mf][nf][half * 2], v1 = a2[mf][nf][half * 2 + 1];
                    if (gc < 32) g_uv2[(size_t)gm * 16 + (gc >> 1)] = pk(v0, v1);
                    else { g_r2[(size_t)gm * 16 + gc - 32] = v0;
                           g_r2[(size_t)gm * 16 + gc - 31] = v1; }
                }
            }
    }
}

// ---------------- aggregation: warp per node, 4 edges/iter via 8-lane groups ------
__global__ __launch_bounds__(256)
void agg_post1(const float* __restrict__ b1) {
    trig();
    int node = (blockIdx.x << 3) + (threadIdx.x >> 5);
    int lane = threadIdx.x & 31;
    int lane8 = lane & 7, grp = lane >> 3;
    int beg = rp(node), end = rp(node + 1);
    float id = g_invdeg[node];
    gds();
    float m[8];
    #pragma unroll
    for (int j = 0; j < 8; j++) m[j] = 0.f;

    auto body = [&](int e) {
        int2 E = g_edge[e];
        float p = __int_as_float(E.y), q = 1.f - p;
        const unsigned* row = g_uv1 + (size_t)E.x * 64 + lane8 * 4;
        uint4 U = *reinterpret_cast<const uint4*>(row);
        uint4 V = *reinterpret_cast<const uint4*>(row + 32);
        float2 u0 = up(U.x), u1 = up(U.y), u2 = up(U.z), u3 = up(U.w);
        float2 v0 = up(V.x), v1 = up(V.y), v2 = up(V.z), v3 = up(V.w);
        m[0] += q * u0.x + p * v0.x;  m[1] += q * u0.y + p * v0.y;
        m[2] += q * u1.x + p * v1.x;  m[3] += q * u1.y + p * v1.y;
        m[4] += q * u2.x + p * v2.x;  m[5] += q * u2.y + p * v2.y;
        m[6] += q * u3.x + p * v3.x;  m[7] += q * u3.y + p * v3.y;
    };

    int e = beg;
    for (; e + 8 <= end; e += 8) { body(e + grp); body(e + 4 + grp); }
    for (; e + 4 <= end; e += 4) body(e + grp);
    if (e + grp < end) body(e + grp);

    #pragma unroll
    for (int o = 8; o <= 16; o <<= 1)
        #pragma unroll
        for (int j = 0; j < 8; j++)
            m[j] += __shfl_xor_sync(0xffffffffu, m[j], o);

    if (grp == 0) {
        size_t ix = (size_t)node * 64 + lane8 * 8;
        float4 r0 = *reinterpret_cast<const float4*>(g_r1 + ix);
        float4 r1 = *reinterpret_cast<const float4*>(g_r1 + ix + 4);
        float h[8];
        #pragma unroll
        for (int j = 0; j < 8; j++) {
            float r = (j < 4) ? (&r0.x)[j] : (&r1.x)[j - 4];
            h[j] = tanhf(m[j] * id + r + b1[lane8 * 8 + j]);
        }
        *reinterpret_cast<float4*>(g_hf + ix)     = make_float4(h[0], h[1], h[2], h[3]);
        *reinterpret_cast<float4*>(g_hf + ix + 4) = make_float4(h[4], h[5], h[6], h[7]);
        uint4 o16 = make_uint4(pk(h[0], h[1]), pk(h[2], h[3]), pk(h[4], h[5]), pk(h[6], h[7]));
        *reinterpret_cast<uint4*>(g_h16 + (size_t)node * 32 + lane8 * 4) = o16;
    }
}

// hidden pre-agg: rows of y are 32 u32; one uint4 per group per edge.
template <int YSEL>  // 0=g_h16, 1=g_a16, 2=g_y16
__global__ __launch_bounds__(256)
void agg_pre() {
    trig();
    int node = (blockIdx.x << 3) + (threadIdx.x >> 5);
    int lane = threadIdx.x & 31;
    int lane8 = lane & 7, grp = lane >> 3;
    int beg = rp(node), end = rp(node + 1);
    float id = g_invdeg[node];
    gds();
    const unsigned* __restrict__ y = (YSEL == 0) ? g_h16 : (YSEL == 1) ? g_a16 : g_y16;
    float a0[8], a1[8];
    #pragma unroll
    for (int j = 0; j < 8; j++) { a0[j] = 0.f; a1[j] = 0.f; }

    auto body = [&](int e) {
        int2 E = g_edge[e];
        float p = __int_as_float(E.y), q = 1.f - p;
        uint4 v = *reinterpret_cast<const uint4*>(y + (size_t)E.x * 32 + lane8 * 4);
        float2 f0 = up(v.x), f1 = up(v.y), f2 = up(v.z), f3 = up(v.w);
        a0[0] += q * f0.x;  a0[1] += q * f0.y;  a0[2] += q * f1.x;  a0[3] += q * f1.y;
        a0[4] += q * f2.x;  a0[5] += q * f2.y;  a0[6] += q * f3.x;  a0[7] += q * f3.y;
        a1[0] += p * f0.x;  a1[1] += p * f0.y;  a1[2] += p * f1.x;  a1[3] += p * f1.y;
        a1[4] += p * f2.x;  a1[5] += p * f2.y;  a1[6] += p * f3.x;  a1[7] += p * f3.y;
    };

    int e = beg;
    for (; e + 8 <= end; e += 8) { body(e + grp); body(e + 4 + grp); }
    for (; e + 4 <= end; e += 4) body(e + grp);
    if (e + grp < end) body(e + grp);

    #pragma unroll
    for (int o = 8; o <= 16; o <<= 1)
        #pragma unroll
        for (int j = 0; j < 8; j++) {
            a0[j] += __shfl_xor_sync(0xffffffffu, a0[j], o);
            a1[j] += __shfl_xor_sync(0xffffffffu, a1[j], o);
        }

    if (grp == 0) {
        uint4 o0 = make_uint4(pk(a0[0] * id, a0[1] * id), pk(a0[2] * id, a0[3] * id),
                              pk(a0[4] * id, a0[5] * id), pk(a0[6] * id, a0[7] * id));
        uint4 o1 = make_uint4(pk(a1[0] * id, a1[1] * id), pk(a1[2] * id, a1[3] * id),
                              pk(a1[4] * id, a1[5] * id), pk(a1[6] * id, a1[7] * id));
        *reinterpret_cast<uint4*>(g_acat + (size_t)node * 64 + lane8 * 4)      = o0;
        *reinterpret_cast<uint4*>(g_acat + (size_t)node * 64 + 32 + lane8 * 4) = o1;
    }
}

// conv2: gather + tanh + log_softmax(16); 16 threads per node
__global__ __launch_bounds__(256)
void conv2_fin(const float* __restrict__ b2, float* __restrict__ out) {
    trig();
    int node = blockIdx.x * 16 + (threadIdx.x >> 4);
    int c = threadIdx.x & 15;
    int beg = rp(node), end = rp(node + 1);
    float id = g_invdeg[node];
    gds();
    float m = 0.f;
    int e = beg;
    for (; e + 2 <= end; e += 2) {
        int2 E0 = g_edge[e], E1 = g_edge[e + 1];
        float p0 = __int_as_float(E0.y), p1 = __int_as_float(E1.y);
        float u0 = bfh(g_uv2[(size_t)E0.x * 16 + (c >> 1)], c & 1);
        float v0 = bfh(g_uv2[(size_t)E0.x * 16 + 8 + (c >> 1)], c & 1);
        float u1 = bfh(g_uv2[(size_t)E1.x * 16 + (c >> 1)], c & 1);
        float v1 = bfh(g_uv2[(size_t)E1.x * 16 + 8 + (c >> 1)], c & 1);
        m += (1.f - p0) * u0 + p0 * v0 + (1.f - p1) * u1 + p1 * v1;
    }
    if (e < end) {
        int2 E0 = g_edge[e];
        float p0 = __int_as_float(E0.y);
        float u = bfh(g_uv2[(size_t)E0.x * 16 + (c >> 1)], c & 1);
        float v = bfh(g_uv2[(size_t)E0.x * 16 + 8 + (c >> 1)], c & 1);
        m += (1.f - p0) * u + p0 * v;
    }
    float o = tanhf(m * id + g_r2[(size_t)node * 16 + c] + b2[c]);
    float mx = o;
    #pragma unroll
    for (int k = 8; k; k >>= 1) mx = fmaxf(mx, __shfl_xor_sync(0xffffffffu, mx, k));
    float s = expf(o - mx);
    float tot = s;
    #pragma unroll
    for (int k = 8; k; k >>= 1) tot += __shfl_xor_sync(0xffffffffu, tot, k);
    out[(size_t)node * 16 + c] = o - mx - logf(tot);
}

// ---------------- launch helpers (PDL on every kernel) ----------------
template <typename F, typename... Args>
static inline void pdl(F f, dim3 grid, dim3 block, Args... args) {
    cudaLaunchConfig_t cfg = {};
    cfg.gridDim = grid;
    cfg.blockDim = block;
    cfg.dynamicSmemBytes = 0;
    cfg.stream = 0;
    cudaLaunchAttribute a[1];
    a[0].id = cudaLaunchAttributeProgrammaticStreamSerialization;
    a[0].val.programmaticStreamSerializationAllowed = 1;
    cfg.attrs = a;
    cfg.numAttrs = 1;
    cudaLaunchKernelEx(&cfg, f, args...);
}

extern "C" void kernel_launch(void* const* d_in, const int* in_sizes, int n_in,
                              void* d_out, int out_size) {
    const float* x   = (const float*)d_in[0];
    const float* ea  = (const float*)d_in[1];
    const int*   src = (const int*)  d_in[2];
    const int*   dst = (const int*)  d_in[3];
    const float* W1  = (const float*)d_in[4];
    const float* R1  = (const float*)d_in[5];
    const float* b1  = (const float*)d_in[6];
    const float* Wa  = (const float*)d_in[7];
    const float* Ra  = (const float*)d_in[8];
    const float* ba  = (const float*)d_in[9];
    const float* Wb  = (const float*)d_in[10];
    const float* Rb  = (const float*)d_in[11];
    const float* bb  = (const float*)d_in[12];
    const float* W2  = (const float*)d_in[13];
    const float* R2  = (const float*)d_in[14];
    const float* b2  = (const float*)d_in[15];
    float* out = (float*)d_out;

    // CSR build + weight/x prep (hist + pack + xpack in one kernel)
    pdl(k_prep, dim3(4057), dim3(256), dst, x, W1, R1, Wa, Ra, Wb, Rb, W2, R2);
    pdl(k_scan, dim3(49), dim3(1024));
    pdl(k_scatter, dim3(3125), dim3(256), src, dst, ea);

    dim3 g1(391, 3), gh(391, 1), ga(6250), gb(256);

    // conv1 GEMM: overlaps scatter (no leading gds); trailing gds joins scatter
    pdl(gemm16<256, 192, 64, M_CONV1>, g1, gb, (const float*)nullptr);
    pdl(agg_post1, ga, gb, b1);

    // RK4: 8 (agg_pre + gemm_h) pairs; last gemm_h also does conv2's GEMM
    pdl(agg_pre<0>, ga, gb);
    pdl(gemm_h<M_PLAIN, 1, 0>, gh, gb, ba);
    pdl(agg_pre<1>, ga, gb);
    pdl(gemm_h<M_K1,    2, 1>, gh, gb, bb);

    pdl(agg_pre<2>, ga, gb);
    pdl(gemm_h<M_PLAIN, 1, 2>, gh, gb, ba);
    pdl(agg_pre<1>, ga, gb);
    pdl(gemm_h<M_K2,    2, 1>, gh, gb, bb);

    pdl(agg_pre<2>, ga, gb);
    pdl(gemm_h<M_PLAIN, 1, 2>, gh, gb, ba);
    pdl(agg_pre<1>, ga, gb);
    pdl(gemm_h<M_K3,    2, 1>, gh, gb, bb);

    pdl(agg_pre<2>, ga, gb);
    pdl(gemm_h<M_PLAIN, 1, 2>, gh, gb, ba);
    pdl(agg_pre<1>, ga, gb);
    pdl(gemm_h<M_K4,    2, 1>, gh, gb, bb);   // + fused conv2 GEMM

    // finish
    pdl(conv2_fin, dim3(3125), gb, b2, out);
}

// round 11
// speedup vs baseline: 1.1435x; 1.0303x over previous
#include <cuda_runtime.h>
#include <cuda_bf16.h>
#include <cstdint>
#include <cstddef>

#define NN 50000
#define NE 800000

// ---------------- static device scratch ----------------
__device__ int   g_cnt[NN];          // histogram (re-zeroed by k_scan each run)
__device__ int   g_cur[NN];          // scatter cursor (re-zeroed by k_scan)
__device__ int   g_rowptr[NN + 1];
__device__ int   g_bsum[64];
__device__ int   g_scan_done;
__device__ __align__(16) int2 g_edge[NE];   // (src, float bits of p)
__device__ float g_invdeg[NN];

// bf16x2-packed tables (u32 each = 2 features)
__device__ __align__(16) unsigned g_x16 [(size_t)NN * 128]; // x pre-packed bf16
__device__ __align__(16) unsigned g_uv1 [(size_t)NN * 64];  // conv1 u|v (128 feats)
__device__ __align__(16) unsigned g_h16 [(size_t)NN * 32];
__device__ __align__(16) unsigned g_a16 [(size_t)NN * 32];
__device__ __align__(16) unsigned g_y16 [(size_t)NN * 32];
__device__ __align__(16) unsigned g_acat[(size_t)NN * 64];  // A0|A1 (128 feats)
__device__ __align__(16) unsigned g_uv2 [(size_t)NN * 16];  // conv2 u|v (32 feats)

// fp32 state
__device__ __align__(16) float g_r1  [(size_t)NN * 64];
__device__ __align__(16) float g_hf  [(size_t)NN * 64];
__device__ __align__(16) float g_accf[(size_t)NN * 64];
__device__ __align__(16) float g_r2  [(size_t)NN * 16];

// packed weights
__device__ unsigned g_wc1[128 * 192];
__device__ unsigned g_wcA[96 * 64];
__device__ unsigned g_wcB[96 * 64];
__device__ unsigned g_wc2[32 * 48];

// ---------------- helpers ----------------
__device__ __forceinline__ void gds() {
#if __CUDA_ARCH__ >= 900
    cudaGridDependencySynchronize();
#endif
}
__device__ __forceinline__ void trig() {
#if __CUDA_ARCH__ >= 900
    cudaTriggerProgrammaticLaunchCompletion();
#endif
}
__device__ __forceinline__ unsigned pk(float a, float b) {
    __nv_bfloat162 h = __floats2bfloat162_rn(a, b);
    return *reinterpret_cast<unsigned*>(&h);
}
__device__ __forceinline__ float2 up(unsigned u) {
    __nv_bfloat162 h = *reinterpret_cast<__nv_bfloat162*>(&u);
    return make_float2(__bfloat162float(h.x), __bfloat162float(h.y));
}
__device__ __forceinline__ float bfh(unsigned u, int hi) {
    unsigned short s = hi ? (unsigned short)(u >> 16) : (unsigned short)(u & 0xffff);
    __nv_bfloat16 b = *reinterpret_cast<__nv_bfloat16*>(&s);
    return __bfloat162float(b);
}
__device__ __forceinline__ int rp(int i) {
    return g_rowptr[i] + g_bsum[i >> 10];
}

// ---------------- prep: edge histogram + weight pack + x bf16 pack ----------------
// NO trig: k_scan (and transitively scatter/conv1) launch only after full
// completion, making conv1's pre-gds reads of g_wc1/g_x16 safe.
__global__ void k_prep(const int* __restrict__ dst, const float* __restrict__ x,
                       const float* __restrict__ W1, const float* __restrict__ R1,
                       const float* __restrict__ Wa, const float* __restrict__ Ra,
                       const float* __restrict__ Wb, const float* __restrict__ Rb,
                       const float* __restrict__ W2, const float* __restrict__ R2) {
    gds();
    if (blockIdx.x < 782) {                       // histogram: 4 edges per thread
        int q = blockIdx.x * 256 + threadIdx.x;
        if (q * 4 < NE) {
            int4 d = *reinterpret_cast<const int4*>(dst + q * 4);
            atomicAdd(&g_cnt[d.x], 1);
            atomicAdd(&g_cnt[d.y], 1);
            atomicAdd(&g_cnt[d.z], 1);
            atomicAdd(&g_cnt[d.w], 1);
        }
        return;
    }
    if (blockIdx.x >= 932) {                      // x -> bf16 pack: 8 u32 per thread
        size_t j = (size_t)(blockIdx.x - 932) * 256 + threadIdx.x;
        size_t ob = j * 8;                         // 800000 threads * 8 = NN*128
        const float4* xp = reinterpret_cast<const float4*>(x + ob * 2);
        float4 v0 = xp[0], v1 = xp[1], v2 = xp[2], v3 = xp[3];
        uint4 o0 = make_uint4(pk(v0.x, v0.y), pk(v0.z, v0.w),
                              pk(v1.x, v1.y), pk(v1.z, v1.w));
        uint4 o1 = make_uint4(pk(v2.x, v2.y), pk(v2.z, v2.w),
                              pk(v3.x, v3.y), pk(v3.z, v3.w));
        reinterpret_cast<uint4*>(g_x16 + ob)[0] = o0;
        reinterpret_cast<uint4*>(g_x16 + ob)[1] = o1;
        return;
    }
    int i = (blockIdx.x - 782) * 256 + threadIdx.x;
    if (i < 24576) {                        // g_wc1 [128][192], K=256
        int k2 = i / 192, c = i % 192;
        int ke = 2 * k2, ko = ke + 1;
        float e, o;
        if (c < 64)       { e = W1[ke * 64 + c];              o = W1[ko * 64 + c]; }
        else if (c < 128) { e = W1[(256 + ke) * 64 + c - 64];  o = W1[(256 + ko) * 64 + c - 64]; }
        else              { e = R1[ke * 64 + c - 128];         o = R1[ko * 64 + c - 128]; }
        g_wc1[i] = pk(e, o);
    } else if (i < 30720) {                 // g_wcA [96][64], K=192
        int j = i - 24576, k2 = j / 64, c = j % 64;
        int ke = 2 * k2, ko = ke + 1;
        float e = (ke < 128) ? Wa[ke * 64 + c] : Ra[(ke - 128) * 64 + c];
        float o = (ko < 128) ? Wa[ko * 64 + c] : Ra[(ko - 128) * 64 + c];
        g_wcA[j] = pk(e, o);
    } else if (i < 36864) {                 // g_wcB
        int j = i - 30720, k2 = j / 64, c = j % 64;
        int ke = 2 * k2, ko = ke + 1;
        float e = (ke < 128) ? Wb[ke * 64 + c] : Rb[(ke - 128) * 64 + c];
        float o = (ko < 128) ? Wb[ko * 64 + c] : Rb[(ko - 128) * 64 + c];
        g_wcB[j] = pk(e, o);
    } else if (i < 38400) {                 // g_wc2 [32][48], K=64
        int j = i - 36864, k2 = j / 48, c = j % 48;
        int ke = 2 * k2, ko = ke + 1;
        float e, o;
        if (c < 16)      { e = W2[ke * 16 + c];              o = W2[ko * 16 + c]; }
        else if (c < 32) { e = W2[(64 + ke) * 16 + c - 16];  o = W2[(64 + ko) * 16 + c - 16]; }
        else             { e = R2[ke * 16 + c - 32];         o = R2[ko * 16 + c - 32]; }
        g_wc2[j] = pk(e, o);
    }
}

// block-local exclusive scan; zero cnt/cur; LAST-finishing block's warp 0 does
// the cross-block scan and resets g_scan_done. NO trig (see k_prep comment).
__global__ void k_scan() {
    gds();
    __shared__ int ws[32];
    __shared__ int is_last;
    int tid = threadIdx.x, lane = tid & 31, wid = tid >> 5;
    int i = blockIdx.x * 1024 + tid;
    int v = (i < NN) ? g_cnt[i] : 0;
    int x = v;
    #pragma unroll
    for (int o = 1; o < 32; o <<= 1) {
        int t = __shfl_up_sync(0xffffffffu, x, o);
        if (lane >= o) x += t;
    }
    if (lane == 31) ws[wid] = x;
    __syncthreads();
    if (wid == 0) {
        int t = ws[lane];
        #pragma unroll
        for (int o = 1; o < 32; o <<= 1) {
            int u = __shfl_up_sync(0xffffffffu, t, o);
            if (lane >= o) t += u;
        }
        ws[lane] = t;
    }
    __syncthreads();
    int excl = x - v + (wid ? ws[wid - 1] : 0);
    if (i < NN) {
        g_rowptr[i] = excl;
        g_invdeg[i] = 1.0f / (float)max(v, 1);
        g_cnt[i] = 0;     // ready for next replay's histogram
        g_cur[i] = 0;     // scatter cursor
    }
    if (tid == 1023) {
        g_bsum[blockIdx.x] = excl + v;
        __threadfence();
        is_last = (atomicAdd(&g_scan_done, 1) == 48);
    }
    __syncthreads();
    if (is_last && tid < 32) {
        __threadfence();   // acquire other blocks' g_bsum writes
        int carry = 0;
        #pragma unroll
        for (int base = 0; base < 64; base += 32) {
            int idx = base + tid;
            int bv = (idx < 49) ? g_bsum[idx] : 0;
            int bx = bv;
            #pragma unroll
            for (int o = 1; o < 32; o <<= 1) {
                int t = __shfl_up_sync(0xffffffffu, bx, o);
                if (tid >= o) bx += t;
            }
            int tot = __shfl_sync(0xffffffffu, bx, 31);
            if (idx < 49) g_bsum[idx] = carry + bx - bv;   // exclusive prefix
            if (idx == 48) g_rowptr[NN] = bv;
            carry += tot;
        }
        if (tid == 0) g_scan_done = 0;   // ready for next replay
    }
}

__global__ void k_scatter(const int* __restrict__ src, const int* __restrict__ dst,
                          const float* __restrict__ ea) {
    trig();   // let conv1 GEMM launch + run concurrently (reads only x16/wc1,
              // both sealed: k_prep completed before k_scan even launched)
    gds();
    int e = blockIdx.x * 256 + threadIdx.x;
    if (e < NE) {
        int d = dst[e];
        int pos = rp(d) + atomicAdd(&g_cur[d], 1);
        g_edge[pos] = make_int2(src[e], __float_as_int(ea[e]));
    }
}

// ---------------- bf16 GEMM (m16n8k16) ----------------
__device__ __forceinline__ void mma16(float* c, unsigned a0, unsigned a1, unsigned a2,
                                      unsigned a3, unsigned b0, unsigned b1) {
    asm volatile(
        "mma.sync.aligned.m16n8k16.row.col.f32.bf16.bf16.f32 "
        "{%0,%1,%2,%3},{%4,%5,%6,%7},{%8,%9},{%0,%1,%2,%3};"
        : "+f"(c[0]), "+f"(c[1]), "+f"(c[2]), "+f"(c[3])
        : "r"(a0), "r"(a1), "r"(a2), "r"(a3), "r"(b0), "r"(b1));
}

constexpr int M_CONV1 = 0, M_PLAIN = 1, M_K1 = 2, M_K2 = 3, M_K3 = 4, M_K4 = 5;

template <int MODE>
__device__ __forceinline__ void epi_row(int gm, int gc, float v0, float v1,
                                        const float* __restrict__ bias) {
    if (gm >= NN) return;
    if constexpr (MODE == M_CONV1) {
        if (gc < 128) g_uv1[(size_t)gm * 64 + (gc >> 1)] = pk(v0, v1);
        else { g_r1[(size_t)gm * 64 + gc - 128] = v0; g_r1[(size_t)gm * 64 + gc - 127] = v1; }
    } else if constexpr (MODE == M_PLAIN) {
        g_a16[(size_t)gm * 32 + (gc >> 1)] = pk(v0 + bias[gc], v1 + bias[gc + 1]);
    } else if constexpr (MODE == M_K1) {
        size_t ix = (size_t)gm * 64 + gc;
        float k0 = v0 + bias[gc], k1 = v1 + bias[gc + 1];
        float h0 = g_hf[ix], h1 = g_hf[ix + 1];
        g_y16[(size_t)gm * 32 + (gc >> 1)] = pk(h0 + 1.5f * k0, h1 + 1.5f * k1);
        g_accf[ix] = h0 + 0.5f * k0; g_accf[ix + 1] = h1 + 0.5f * k1;
    } else if constexpr (MODE == M_K2) {
        size_t ix = (size_t)gm * 64 + gc;
        float k0 = v0 + bias[gc], k1 = v1 + bias[gc + 1];
        float h0 = g_hf[ix], h1 = g_hf[ix + 1];
        g_y16[(size_t)gm * 32 + (gc >> 1)] = pk(h0 + 1.5f * k0, h1 + 1.5f * k1);
        g_accf[ix] += k0; g_accf[ix + 1] += k1;
    } else if constexpr (MODE == M_K3) {
        size_t ix = (size_t)gm * 64 + gc;
        float k0 = v0 + bias[gc], k1 = v1 + bias[gc + 1];
        float h0 = g_hf[ix], h1 = g_hf[ix + 1];
        g_y16[(size_t)gm * 32 + (gc >> 1)] = pk(h0 + 3.0f * k0, h1 + 3.0f * k1);
        g_accf[ix] += k0; g_accf[ix + 1] += k1;
    }
}

// conv1 GEMM with register-prefetch software pipeline; reads pre-packed bf16 x.
// trig at entry (downstream preamble-safe); trailing gds joins scatter.
template <int K, int NOUT, int BN, int MODE>
__global__ __launch_bounds__(256)
void gemm16(const float* __restrict__ bias) {
    trig();
    constexpr int NF = BN / 16;
    __shared__ __align__(16) unsigned As[128][36];
    __shared__ unsigned Bs[32][72];

    const unsigned* Wp = g_wc1;

    const int tid = threadIdx.x;
    const int m0 = blockIdx.x * 128;
    const int n0 = blockIdx.y * BN;
    const int wid = tid >> 5, lane = tid & 31;
    const int wm = (wid & 3) * 32;
    const int wn = (wid >> 2) * (BN / 2);
    const int g = lane >> 2, t = lane & 3;

    float acc[2][NF][4];
    #pragma unroll
    for (int i = 0; i < 2; i++)
        #pragma unroll
        for (int j = 0; j < NF; j++)
            #pragma unroll
            for (int e = 0; e < 4; e++) acc[i][j][e] = 0.f;

    uint4 aReg[4];
    unsigned bReg[8];
    auto loadA = [&](int kc) {
        #pragma unroll
        for (int i = 0; i < 4; i++) {
            int q = tid + i * 256;
            int row = q >> 3, q4 = q & 7;
            int gm = m0 + row;
            aReg[i] = make_uint4(0, 0, 0, 0);
            if (gm < NN)
                aReg[i] = *reinterpret_cast<const uint4*>(
                              g_x16 + (size_t)gm * 128 + kc / 2 + q4 * 4);
        }
    };
    auto loadB = [&](int kc) {
        #pragma unroll
        for (int i = 0; i < 8; i++) {
            int q = tid + i * 256;
            int r = q >> 6, n = q & 63;
            bReg[i] = Wp[(size_t)(kc / 2 + r) * NOUT + n0 + n];
        }
    };

    loadA(0); loadB(0);
    for (int kc = 0; kc < K; kc += 64) {
        __syncthreads();   // previous chunk's mma reads finished
        #pragma unroll
        for (int i = 0; i < 4; i++) {
            int q = tid + i * 256;
            *reinterpret_cast<uint4*>(&As[q >> 3][(q & 7) * 4]) = aReg[i];
        }
        #pragma unroll
        for (int i = 0; i < 8; i++) {
            int q = tid + i * 256;
            Bs[q >> 6][q & 63] = bReg[i];
        }
        if (kc + 64 < K) { loadA(kc + 64); loadB(kc + 64); }  // overlaps mma below
        __syncthreads();
        #pragma unroll
        for (int ks = 0; ks < 4; ks++) {
            const int kb = ks * 8;
            unsigned a[2][4];
            #pragma unroll
            for (int mf = 0; mf < 2; mf++) {
                a[mf][0] = As[wm + mf * 16 + g    ][kb + t];
                a[mf][1] = As[wm + mf * 16 + g + 8][kb + t];
                a[mf][2] = As[wm + mf * 16 + g    ][kb + 4 + t];
                a[mf][3] = As[wm + mf * 16 + g + 8][kb + 4 + t];
            }
            unsigned b[NF][2];
            #pragma unroll
            for (int nf = 0; nf < NF; nf++) {
                b[nf][0] = Bs[kb + t    ][wn + nf * 8 + g];
                b[nf][1] = Bs[kb + 4 + t][wn + nf * 8 + g];
            }
            #pragma unroll
            for (int mf = 0; mf < 2; mf++)
                #pragma unroll
                for (int nf = 0; nf < NF; nf++)
                    mma16(acc[mf][nf], a[mf][0], a[mf][1], a[mf][2], a[mf][3],
                          b[nf][0], b[nf][1]);
        }
    }

    #pragma unroll
    for (int mf = 0; mf < 2; mf++)
        #pragma unroll
        for (int nf = 0; nf < NF; nf++) {
            int gm0 = m0 + wm + mf * 16 + g;
            int gc  = n0 + wn + nf * 8 + t * 2;
            epi_row<MODE>(gm0,     gc, acc[mf][nf][0], acc[mf][nf][1], bias);
            epi_row<MODE>(gm0 + 8, gc, acc[mf][nf][2], acc[mf][nf][3], bias);
        }
    gds();   // join with scatter: completion implies both
}

// ---------------- hidden GEMM: weight preload pre-gds + A register prefetch -------
// MODE == M_K4 additionally runs the fused conv2 GEMM on the fresh h_new tile.
template <int MODE, int WSEL, int YSEL>
__global__ __launch_bounds__(256)
void gemm_h(const float* __restrict__ bias) {
    trig();
    __shared__ __align__(16) unsigned As[128][36];
    __shared__ unsigned Bs[96][72];
    const unsigned* Wp = (WSEL == 1) ? g_wcA : g_wcB;
    const int tid = threadIdx.x;
    // preamble: full 96x64 weight matrix to smem (sealed before RK phase)
    #pragma unroll
    for (int i = 0; i < 24; i++) {
        int q = tid + i * 256;
        Bs[q >> 6][q & 63] = Wp[q];
    }
    gds();
    const unsigned* __restrict__ y = (YSEL == 0) ? g_h16 : (YSEL == 1) ? g_a16 : g_y16;
    const int m0 = blockIdx.x * 128;
    const int wid = tid >> 5, lane = tid & 31;
    const int wm = (wid & 3) * 32, wn = (wid >> 2) * 32;
    const int g = lane >> 2, t = lane & 3;

    float acc[2][4][4];
    #pragma unroll
    for (int i = 0; i < 2; i++)
        #pragma unroll
        for (int j = 0; j < 4; j++)
            #pragma unroll
            for (int e = 0; e < 4; e++) acc[i][j][e] = 0.f;

    uint4 aReg[4];
    auto loadA = [&](int chunk) {
        #pragma unroll
        for (int i = 0; i < 4; i++) {
            int q = tid + i * 256;
            int row = q >> 3, q4 = q & 7;
            int gm = m0 + row;
            aReg[i] = make_uint4(0, 0, 0, 0);
            if (gm < NN) {
                const unsigned* p = (chunk == 0) ? g_acat + (size_t)gm * 64 + q4 * 4
                                  : (chunk == 1) ? g_acat + (size_t)gm * 64 + 32 + q4 * 4
                                  :                y + (size_t)gm * 32 + q4 * 4;
                aReg[i] = *reinterpret_cast<const uint4*>(p);
            }
        }
    };

    loadA(0);
    #pragma unroll
    for (int chunk = 0; chunk < 3; chunk++) {
        __syncthreads();
        #pragma unroll
        for (int i = 0; i < 4; i++) {
            int q = tid + i * 256;
            *reinterpret_cast<uint4*>(&As[q >> 3][(q & 7) * 4]) = aReg[i];
        }
        if (chunk < 2) loadA(chunk + 1);   // overlaps mma below
        __syncthreads();
        const int c32 = chunk * 32;
        #pragma unroll
        for (int ks = 0; ks < 4; ks++) {
            const int kb = ks * 8;
            unsigned a[2][4];
            #pragma unroll
            for (int mf = 0; mf < 2; mf++) {
                a[mf][0] = As[wm + mf * 16 + g    ][kb + t];
                a[mf][1] = As[wm + mf * 16 + g + 8][kb + t];
                a[mf][2] = As[wm + mf * 16 + g    ][kb + 4 + t];
                a[mf][3] = As[wm + mf * 16 + g + 8][kb + 4 + t];
            }
            unsigned b[4][2];
            #pragma unroll
            for (int nf = 0; nf < 4; nf++) {
                b[nf][0] = Bs[c32 + kb + t    ][wn + nf * 8 + g];
                b[nf][1] = Bs[c32 + kb + 4 + t][wn + nf * 8 + g];
            }
            #pragma unroll
            for (int mf = 0; mf < 2; mf++)
                #pragma unroll
                for (int nf = 0; nf < 4; nf++)
                    mma16(acc[mf][nf], a[mf][0], a[mf][1], a[mf][2], a[mf][3],
                          b[nf][0], b[nf][1]);
        }
    }

    if constexpr (MODE != M_K4) {
        #pragma unroll
        for (int mf = 0; mf < 2; mf++)
            #pragma unroll
            for (int nf = 0; nf < 4; nf++) {
                int gm0 = m0 + wm + mf * 16 + g;
                int gc  = wn + nf * 8 + t * 2;
                epi_row<MODE>(gm0,     gc, acc[mf][nf][0], acc[mf][nf][1], bias);
                epi_row<MODE>(gm0 + 8, gc, acc[mf][nf][2], acc[mf][nf][3], bias);
            }
    } else {
        // ---- fused: h_new into As (bf16), then conv2 GEMM (K=64, N=48) ----
        __syncthreads();   // all mma reads of As/Bs done
        #pragma unroll
        for (int mf = 0; mf < 2; mf++)
            #pragma unroll
            for (int nf = 0; nf < 4; nf++) {
                #pragma unroll
                for (int half = 0; half < 2; half++) {
                    int row = wm + mf * 16 + g + half * 8;
                    int gm  = m0 + row;
                    int gc  = wn + nf * 8 + t * 2;
                    float hn0 = 0.f, hn1 = 0.f;
                    if (gm < NN) {
                        size_t ix = (size_t)gm * 64 + gc;
                        float k0 = acc[mf][nf][half * 2]     + bias[gc];
                        float k1 = acc[mf][nf][half * 2 + 1] + bias[gc + 1];
                        hn0 = g_accf[ix]     + 0.5f * k0;
                        hn1 = g_accf[ix + 1] + 0.5f * k1;
                    }
                    As[row][gc >> 1] = pk(hn0, hn1);
                }
            }
        #pragma unroll
        for (int i = 0; i < 6; i++) {
            int q = tid + i * 256;
            Bs[q / 48][q % 48] = g_wc2[q];
        }
        __syncthreads();

        const int wn2 = (wid >> 2) * 24;
        float a2[2][3][4];
        #pragma unroll
        for (int i = 0; i < 2; i++)
            #pragma unroll
            for (int j = 0; j < 3; j++)
                #pragma unroll
                for (int e = 0; e < 4; e++) a2[i][j][e] = 0.f;

        #pragma unroll
        for (int ks = 0; ks < 4; ks++) {
            const int kb = ks * 8;
            unsigned a[2][4];
            #pragma unroll
            for (int mf = 0; mf < 2; mf++) {
                a[mf][0] = As[wm + mf * 16 + g    ][kb + t];
                a[mf][1] = As[wm + mf * 16 + g + 8][kb + t];
                a[mf][2] = As[wm + mf * 16 + g    ][kb + 4 + t];
                a[mf][3] = As[wm + mf * 16 + g + 8][kb + 4 + t];
            }
            unsigned b[3][2];
            #pragma unroll
            for (int nf = 0; nf < 3; nf++) {
                b[nf][0] = Bs[kb + t    ][wn2 + nf * 8 + g];
                b[nf][1] = Bs[kb + 4 + t][wn2 + nf * 8 + g];
            }
            #pragma unroll
            for (int mf = 0; mf < 2; mf++)
                #pragma unroll
                for (int nf = 0; nf < 3; nf++)
                    mma16(a2[mf][nf], a[mf][0], a[mf][1], a[mf][2], a[mf][3],
                          b[nf][0], b[nf][1]);
        }

        #pragma unroll
        for (int mf = 0; mf < 2; mf++)
            #pragma unroll
            for (int nf = 0; nf < 3; nf++) {
                #pragma unroll
                for (int half = 0; half < 2; half++) {
                    int gm = m0 + wm + mf * 16 + g + half * 8;
                    int gc = wn2 + nf * 8 + t * 2;
                    if (gm >= NN) continue;
                    float v0 = a2[mf][nf][half * 2], v1 = a2[mf][nf][half * 2 + 1];
                    if (gc < 32) g_uv2[(size_t)gm * 16 + (gc >> 1)] = pk(v0, v1);
                    else { g_r2[(size_t)gm * 16 + gc - 32] = v0;
                           g_r2[(size_t)gm * 16 + gc - 31] = v1; }
                }
            }
    }
}

// ---------------- aggregation: warp per node, 4 edges/iter via 8-lane groups ------
__global__ __launch_bounds__(256)
void agg_post1(const float* __restrict__ b1) {
    trig();
    int node = (blockIdx.x << 3) + (threadIdx.x >> 5);
    int lane = threadIdx.x & 31;
    int lane8 = lane & 7, grp = lane >> 3;
    int beg = rp(node), end = rp(node + 1);
    float id = g_invdeg[node];
    gds();
    float m[8];
    #pragma unroll
    for (int j = 0; j < 8; j++) m[j] = 0.f;

    auto body = [&](int e) {
        int2 E = g_edge[e];
        float p = __int_as_float(E.y), q = 1.f - p;
        const unsigned* row = g_uv1 + (size_t)E.x * 64 + lane8 * 4;
        uint4 U = *reinterpret_cast<const uint4*>(row);
        uint4 V = *reinterpret_cast<const uint4*>(row + 32);
        float2 u0 = up(U.x), u1 = up(U.y), u2 = up(U.z), u3 = up(U.w);
        float2 v0 = up(V.x), v1 = up(V.y), v2 = up(V.z), v3 = up(V.w);
        m[0] += q * u0.x + p * v0.x;  m[1] += q * u0.y + p * v0.y;
        m[2] += q * u1.x + p * v1.x;  m[3] += q * u1.y + p * v1.y;
        m[4] += q * u2.x + p * v2.x;  m[5] += q * u2.y + p * v2.y;
        m[6] += q * u3.x + p * v3.x;  m[7] += q * u3.y + p * v3.y;
    };

    int e = beg;
    for (; e + 8 <= end; e += 8) { body(e + grp); body(e + 4 + grp); }
    for (; e + 4 <= end; e += 4) body(e + grp);
    if (e + grp < end) body(e + grp);

    #pragma unroll
    for (int o = 8; o <= 16; o <<= 1)
        #pragma unroll
        for (int j = 0; j < 8; j++)
            m[j] += __shfl_xor_sync(0xffffffffu, m[j], o);

    if (grp == 0) {
        size_t ix = (size_t)node * 64 + lane8 * 8;
        float4 r0 = *reinterpret_cast<const float4*>(g_r1 + ix);
        float4 r1 = *reinterpret_cast<const float4*>(g_r1 + ix + 4);
        float h[8];
        #pragma unroll
        for (int j = 0; j < 8; j++) {
            float r = (j < 4) ? (&r0.x)[j] : (&r1.x)[j - 4];
            h[j] = tanhf(m[j] * id + r + b1[lane8 * 8 + j]);
        }
        *reinterpret_cast<float4*>(g_hf + ix)     = make_float4(h[0], h[1], h[2], h[3]);
        *reinterpret_cast<float4*>(g_hf + ix + 4) = make_float4(h[4], h[5], h[6], h[7]);
        uint4 o16 = make_uint4(pk(h[0], h[1]), pk(h[2], h[3]), pk(h[4], h[5]), pk(h[6], h[7]));
        *reinterpret_cast<uint4*>(g_h16 + (size_t)node * 32 + lane8 * 4) = o16;
    }
}

// hidden pre-agg: rows of y are 32 u32; one uint4 per group per edge.
template <int YSEL>  // 0=g_h16, 1=g_a16, 2=g_y16
__global__ __launch_bounds__(256)
void agg_pre() {
    trig();
    int node = (blockIdx.x << 3) + (threadIdx.x >> 5);
    int lane = threadIdx.x & 31;
    int lane8 = lane & 7, grp = lane >> 3;
    int beg = rp(node), end = rp(node + 1);
    float id = g_invdeg[node];
    gds();
    const unsigned* __restrict__ y = (YSEL == 0) ? g_h16 : (YSEL == 1) ? g_a16 : g_y16;
    float a0[8], a1[8];
    #pragma unroll
    for (int j = 0; j < 8; j++) { a0[j] = 0.f; a1[j] = 0.f; }

    auto body = [&](int e) {
        int2 E = g_edge[e];
        float p = __int_as_float(E.y), q = 1.f - p;
        uint4 v = *reinterpret_cast<const uint4*>(y + (size_t)E.x * 32 + lane8 * 4);
        float2 f0 = up(v.x), f1 = up(v.y), f2 = up(v.z), f3 = up(v.w);
        a0[0] += q * f0.x;  a0[1] += q * f0.y;  a0[2] += q * f1.x;  a0[3] += q * f1.y;
        a0[4] += q * f2.x;  a0[5] += q * f2.y;  a0[6] += q * f3.x;  a0[7] += q * f3.y;
        a1[0] += p * f0.x;  a1[1] += p * f0.y;  a1[2] += p * f1.x;  a1[3] += p * f1.y;
        a1[4] += p * f2.x;  a1[5] += p * f2.y;  a1[6] += p * f3.x;  a1[7] += p * f3.y;
    };

    int e = beg;
    for (; e + 8 <= end; e += 8) { body(e + grp); body(e + 4 + grp); }
    for (; e + 4 <= end; e += 4) body(e + grp);
    if (e + grp < end) body(e + grp);

    #pragma unroll
    for (int o = 8; o <= 16; o <<= 1)
        #pragma unroll
        for (int j = 0; j < 8; j++) {
            a0[j] += __shfl_xor_sync(0xffffffffu, a0[j], o);
            a1[j] += __shfl_xor_sync(0xffffffffu, a1[j], o);
        }

    if (grp == 0) {
        uint4 o0 = make_uint4(pk(a0[0] * id, a0[1] * id), pk(a0[2] * id, a0[3] * id),
                              pk(a0[4] * id, a0[5] * id), pk(a0[6] * id, a0[7] * id));
        uint4 o1 = make_uint4(pk(a1[0] * id, a1[1] * id), pk(a1[2] * id, a1[3] * id),
                              pk(a1[4] * id, a1[5] * id), pk(a1[6] * id, a1[7] * id));
        *reinterpret_cast<uint4*>(g_acat + (size_t)node * 64 + lane8 * 4)      = o0;
        *reinterpret_cast<uint4*>(g_acat + (size_t)node * 64 + 32 + lane8 * 4) = o1;
    }
}

// conv2: gather + tanh + log_softmax(16); 16 threads per node
__global__ __launch_bounds__(256)
void conv2_fin(const float* __restrict__ b2, float* __restrict__ out) {
    trig();
    int node = blockIdx.x * 16 + (threadIdx.x >> 4);
    int c = threadIdx.x & 15;
    int beg = rp(node), end = rp(node + 1);
    float id = g_invdeg[node];
    gds();
    float m = 0.f;
    int e = beg;
    for (; e + 2 <= end; e += 2) {
        int2 E0 = g_edge[e], E1 = g_edge[e + 1];
        float p0 = __int_as_float(E0.y), p1 = __int_as_float(E1.y);
        float u0 = bfh(g_uv2[(size_t)E0.x * 16 + (c >> 1)], c & 1);
        float v0 = bfh(g_uv2[(size_t)E0.x * 16 + 8 + (c >> 1)], c & 1);
        float u1 = bfh(g_uv2[(size_t)E1.x * 16 + (c >> 1)], c & 1);
        float v1 = bfh(g_uv2[(size_t)E1.x * 16 + 8 + (c >> 1)], c & 1);
        m += (1.f - p0) * u0 + p0 * v0 + (1.f - p1) * u1 + p1 * v1;
    }
    if (e < end) {
        int2 E0 = g_edge[e];
        float p0 = __int_as_float(E0.y);
        float u = bfh(g_uv2[(size_t)E0.x * 16 + (c >> 1)], c & 1);
        float v = bfh(g_uv2[(size_t)E0.x * 16 + 8 + (c >> 1)], c & 1);
        m += (1.f - p0) * u + p0 * v;
    }
    float o = tanhf(m * id + g_r2[(size_t)node * 16 + c] + b2[c]);
    float mx = o;
    #pragma unroll
    for (int k = 8; k; k >>= 1) mx = fmaxf(mx, __shfl_xor_sync(0xffffffffu, mx, k));
    float s = expf(o - mx);
    float tot = s;
    #pragma unroll
    for (int k = 8; k; k >>= 1) tot += __shfl_xor_sync(0xffffffffu, tot, k);
    out[(size_t)node * 16 + c] = o - mx - logf(tot);
}

// ---------------- launch helpers (PDL on every kernel) ----------------
template <typename F, typename... Args>
static inline void pdl(F f, dim3 grid, dim3 block, Args... args) {
    cudaLaunchConfig_t cfg = {};
    cfg.gridDim = grid;
    cfg.blockDim = block;
    cfg.dynamicSmemBytes = 0;
    cfg.stream = 0;
    cudaLaunchAttribute a[1];
    a[0].id = cudaLaunchAttributeProgrammaticStreamSerialization;
    a[0].val.programmaticStreamSerializationAllowed = 1;
    cfg.attrs = a;
    cfg.numAttrs = 1;
    cudaLaunchKernelEx(&cfg, f, args...);
}

extern "C" void kernel_launch(void* const* d_in, const int* in_sizes, int n_in,
                              void* d_out, int out_size) {
    const float* x   = (const float*)d_in[0];
    const float* ea  = (const float*)d_in[1];
    const int*   src = (const int*)  d_in[2];
    const int*   dst = (const int*)  d_in[3];
    const float* W1  = (const float*)d_in[4];
    const float* R1  = (const float*)d_in[5];
    const float* b1  = (const float*)d_in[6];
    const float* Wa  = (const float*)d_in[7];
    const float* Ra  = (const float*)d_in[8];
    const float* ba  = (const float*)d_in[9];
    const float* Wb  = (const float*)d_in[10];
    const float* Rb  = (const float*)d_in[11];
    const float* bb  = (const float*)d_in[12];
    const float* W2  = (const float*)d_in[13];
    const float* R2  = (const float*)d_in[14];
    const float* b2  = (const float*)d_in[15];
    float* out = (float*)d_out;

    // CSR build + weight/x prep (hist + pack + xpack in one kernel)
    pdl(k_prep, dim3(4057), dim3(256), dst, x, W1, R1, Wa, Ra, Wb, Rb, W2, R2);
    pdl(k_scan, dim3(49), dim3(1024));
    pdl(k_scatter, dim3(3125), dim3(256), src, dst, ea);

    dim3 g1(391, 3), gh(391, 1), ga(6250), gb(256);

    // conv1 GEMM: overlaps scatter (no leading gds); trailing gds joins scatter
    pdl(gemm16<256, 192, 64, M_CONV1>, g1, gb, (const float*)nullptr);
    pdl(agg_post1, ga, gb, b1);

    // RK4: 8 (agg_pre + gemm_h) pairs; last gemm_h also does conv2's GEMM
    pdl(agg_pre<0>, ga, gb);
    pdl(gemm_h<M_PLAIN, 1, 0>, gh, gb, ba);
    pdl(agg_pre<1>, ga, gb);
    pdl(gemm_h<M_K1,    2, 1>, gh, gb, bb);

    pdl(agg_pre<2>, ga, gb);
    pdl(gemm_h<M_PLAIN, 1, 2>, gh, gb, ba);
    pdl(agg_pre<1>, ga, gb);
    pdl(gemm_h<M_K2,    2, 1>, gh, gb, bb);

    pdl(agg_pre<2>, ga, gb);
    pdl(gemm_h<M_PLAIN, 1, 2>, gh, gb, ba);
    pdl(agg_pre<1>, ga, gb);
    pdl(gemm_h<M_K3,    2, 1>, gh, gb, bb);

    pdl(agg_pre<2>, ga, gb);
    pdl(gemm_h<M_PLAIN, 1, 2>, gh, gb, ba);
    pdl(agg_pre<1>, ga, gb);
    pdl(gemm_h<M_K4,    2, 1>, gh, gb, bb);   // + fused conv2 GEMM

    // finish
    pdl(conv2_fin, dim3(3125), gb, b2, out);
}

// round 12
// speedup vs baseline: 1.1446x; 1.0010x over previous
#include <cuda_runtime.h>
#include <cuda_bf16.h>
#include <cstdint>
#include <cstddef>

#define NN 50000
#define NE 800000

// ---------------- static device scratch ----------------
__device__ int   g_cnt[NN];          // histogram (re-zeroed by k_scan each run)
__device__ int   g_cur[NN];          // scatter cursor (re-zeroed by k_scan)
__device__ int   g_rowptr[NN + 1];
__device__ int   g_bsum[64];
__device__ int   g_scan_done;
__device__ __align__(16) int2 g_edge[NE];   // (src, float bits of p)
__device__ float g_invdeg[NN];

// bf16x2-packed tables (u32 each = 2 features)
__device__ __align__(16) unsigned g_x16 [(size_t)NN * 128]; // x pre-packed bf16
__device__ __align__(16) unsigned g_uv1 [(size_t)NN * 64];  // conv1 u|v (128 feats)
__device__ __align__(16) unsigned g_h16 [(size_t)NN * 32];
__device__ __align__(16) unsigned g_a16 [(size_t)NN * 32];
__device__ __align__(16) unsigned g_y16 [(size_t)NN * 32];
__device__ __align__(16) unsigned g_acat[(size_t)NN * 64];  // A0|A1 (128 feats)
__device__ __align__(16) unsigned g_uv2 [(size_t)NN * 16];  // conv2 u|v (32 feats)

// fp32 state
__device__ __align__(16) float g_r1  [(size_t)NN * 64];
__device__ __align__(16) float g_hf  [(size_t)NN * 64];
__device__ __align__(16) float g_accf[(size_t)NN * 64];
__device__ __align__(16) float g_r2  [(size_t)NN * 16];

// packed weights
__device__ unsigned g_wc1[128 * 192];
__device__ unsigned g_wcA[96 * 64];
__device__ unsigned g_wcB[96 * 64];
__device__ unsigned g_wc2[32 * 48];

// ---------------- helpers ----------------
__device__ __forceinline__ void gds() {
#if __CUDA_ARCH__ >= 900
    cudaGridDependencySynchronize();
#endif
}
__device__ __forceinline__ void trig() {
#if __CUDA_ARCH__ >= 900
    cudaTriggerProgrammaticLaunchCompletion();
#endif
}
__device__ __forceinline__ unsigned pk(float a, float b) {
    __nv_bfloat162 h = __floats2bfloat162_rn(a, b);
    return *reinterpret_cast<unsigned*>(&h);
}
__device__ __forceinline__ float2 up(unsigned u) {
    __nv_bfloat162 h = *reinterpret_cast<__nv_bfloat162*>(&u);
    return make_float2(__bfloat162float(h.x), __bfloat162float(h.y));
}
__device__ __forceinline__ float bfh(unsigned u, int hi) {
    unsigned short s = hi ? (unsigned short)(u >> 16) : (unsigned short)(u & 0xffff);
    __nv_bfloat16 b = *reinterpret_cast<__nv_bfloat16*>(&s);
    return __bfloat162float(b);
}
__device__ __forceinline__ int rp(int i) {
    return g_rowptr[i] + g_bsum[i >> 10];
}

// ---------------- prep: edge histogram + weight pack + x bf16 pack ----------------
// NO trig: k_scan launches only at full completion -> downstream pre-gds reads
// of g_wc1/g_wcA/g_wcB/g_x16 are safe.
__global__ void k_prep(const int* __restrict__ dst, const float* __restrict__ x,
                       const float* __restrict__ W1, const float* __restrict__ R1,
                       const float* __restrict__ Wa, const float* __restrict__ Ra,
                       const float* __restrict__ Wb, const float* __restrict__ Rb,
                       const float* __restrict__ W2, const float* __restrict__ R2) {
    gds();
    if (blockIdx.x < 782) {                       // histogram: 4 edges per thread
        int q = blockIdx.x * 256 + threadIdx.x;
        if (q * 4 < NE) {
            int4 d = *reinterpret_cast<const int4*>(dst + q * 4);
            atomicAdd(&g_cnt[d.x], 1);
            atomicAdd(&g_cnt[d.y], 1);
            atomicAdd(&g_cnt[d.z], 1);
            atomicAdd(&g_cnt[d.w], 1);
        }
        return;
    }
    if (blockIdx.x >= 932) {                      // x -> bf16 pack: 8 u32 per thread
        size_t j = (size_t)(blockIdx.x - 932) * 256 + threadIdx.x;
        size_t ob = j * 8;                         // 800000 threads * 8 = NN*128
        const float4* xp = reinterpret_cast<const float4*>(x + ob * 2);
        float4 v0 = xp[0], v1 = xp[1], v2 = xp[2], v3 = xp[3];
        uint4 o0 = make_uint4(pk(v0.x, v0.y), pk(v0.z, v0.w),
                              pk(v1.x, v1.y), pk(v1.z, v1.w));
        uint4 o1 = make_uint4(pk(v2.x, v2.y), pk(v2.z, v2.w),
                              pk(v3.x, v3.y), pk(v3.z, v3.w));
        reinterpret_cast<uint4*>(g_x16 + ob)[0] = o0;
        reinterpret_cast<uint4*>(g_x16 + ob)[1] = o1;
        return;
    }
    int i = (blockIdx.x - 782) * 256 + threadIdx.x;
    if (i < 24576) {                        // g_wc1 [128][192], K=256
        int k2 = i / 192, c = i % 192;
        int ke = 2 * k2, ko = ke + 1;
        float e, o;
        if (c < 64)       { e = W1[ke * 64 + c];              o = W1[ko * 64 + c]; }
        else if (c < 128) { e = W1[(256 + ke) * 64 + c - 64];  o = W1[(256 + ko) * 64 + c - 64]; }
        else              { e = R1[ke * 64 + c - 128];         o = R1[ko * 64 + c - 128]; }
        g_wc1[i] = pk(e, o);
    } else if (i < 30720) {                 // g_wcA [96][64], K=192
        int j = i - 24576, k2 = j / 64, c = j % 64;
        int ke = 2 * k2, ko = ke + 1;
        float e = (ke < 128) ? Wa[ke * 64 + c] : Ra[(ke - 128) * 64 + c];
        float o = (ko < 128) ? Wa[ko * 64 + c] : Ra[(ko - 128) * 64 + c];
        g_wcA[j] = pk(e, o);
    } else if (i < 36864) {                 // g_wcB
        int j = i - 30720, k2 = j / 64, c = j % 64;
        int ke = 2 * k2, ko = ke + 1;
        float e = (ke < 128) ? Wb[ke * 64 + c] : Rb[(ke - 128) * 64 + c];
        float o = (ko < 128) ? Wb[ko * 64 + c] : Rb[(ko - 128) * 64 + c];
        g_wcB[j] = pk(e, o);
    } else if (i < 38400) {                 // g_wc2 [32][48], K=64
        int j = i - 36864, k2 = j / 48, c = j % 48;
        int ke = 2 * k2, ko = ke + 1;
        float e, o;
        if (c < 16)      { e = W2[ke * 16 + c];              o = W2[ko * 16 + c]; }
        else if (c < 32) { e = W2[(64 + ke) * 16 + c - 16];  o = W2[(64 + ko) * 16 + c - 16]; }
        else             { e = R2[ke * 16 + c - 32];         o = R2[ko * 16 + c - 32]; }
        g_wc2[j] = pk(e, o);
    }
}

// block-local exclusive scan; zero cnt/cur; LAST-finishing block's warp 0 does
// the cross-block scan. Entry trig: lets scatter->conv1 cascade launch so conv1
// overlaps the scan itself (conv1 needs only k_prep, which completed before
// this kernel launched). Downstream kernels must NOT read scan outputs pre-gds.
__global__ void k_scan() {
    trig();
    gds();
    __shared__ int ws[32];
    __shared__ int is_last;
    int tid = threadIdx.x, lane = tid & 31, wid = tid >> 5;
    int i = blockIdx.x * 1024 + tid;
    int v = (i < NN) ? g_cnt[i] : 0;
    int x = v;
    #pragma unroll
    for (int o = 1; o < 32; o <<= 1) {
        int t = __shfl_up_sync(0xffffffffu, x, o);
        if (lane >= o) x += t;
    }
    if (lane == 31) ws[wid] = x;
    __syncthreads();
    if (wid == 0) {
        int t = ws[lane];
        #pragma unroll
        for (int o = 1; o < 32; o <<= 1) {
            int u = __shfl_up_sync(0xffffffffu, t, o);
            if (lane >= o) t += u;
        }
        ws[lane] = t;
    }
    __syncthreads();
    int excl = x - v + (wid ? ws[wid - 1] : 0);
    if (i < NN) {
        g_rowptr[i] = excl;
        g_invdeg[i] = 1.0f / (float)max(v, 1);
        g_cnt[i] = 0;     // ready for next replay's histogram
        g_cur[i] = 0;     // scatter cursor
    }
    if (tid == 1023) {
        g_bsum[blockIdx.x] = excl + v;
        __threadfence();
        is_last = (atomicAdd(&g_scan_done, 1) == 48);
    }
    __syncthreads();
    if (is_last && tid < 32) {
        __threadfence();   // acquire other blocks' g_bsum writes
        int carry = 0;
        #pragma unroll
        for (int base = 0; base < 64; base += 32) {
            int idx = base + tid;
            int bv = (idx < 49) ? g_bsum[idx] : 0;
            int bx = bv;
            #pragma unroll
            for (int o = 1; o < 32; o <<= 1) {
                int t = __shfl_up_sync(0xffffffffu, bx, o);
                if (tid >= o) bx += t;
            }
            int tot = __shfl_sync(0xffffffffu, bx, 31);
            if (idx < 49) g_bsum[idx] = carry + bx - bv;   // exclusive prefix
            if (idx == 48) g_rowptr[NN] = bv;
            carry += tot;
        }
        if (tid == 0) g_scan_done = 0;   // ready for next replay
    }
}

__global__ void k_scatter(const int* __restrict__ src, const int* __restrict__ dst,
                          const float* __restrict__ ea) {
    trig();   // cascades conv1 launch (conv1 reads only x16/wc1, prep-sealed)
    gds();
    int e = blockIdx.x * 256 + threadIdx.x;
    if (e < NE) {
        int d = dst[e];
        int pos = rp(d) + atomicAdd(&g_cur[d], 1);
        g_edge[pos] = make_int2(src[e], __float_as_int(ea[e]));
    }
}

// ---------------- bf16 GEMM (m16n8k16) ----------------
__device__ __forceinline__ void mma16(float* c, unsigned a0, unsigned a1, unsigned a2,
                                      unsigned a3, unsigned b0, unsigned b1) {
    asm volatile(
        "mma.sync.aligned.m16n8k16.row.col.f32.bf16.bf16.f32 "
        "{%0,%1,%2,%3},{%4,%5,%6,%7},{%8,%9},{%0,%1,%2,%3};"
        : "+f"(c[0]), "+f"(c[1]), "+f"(c[2]), "+f"(c[3])
        : "r"(a0), "r"(a1), "r"(a2), "r"(a3), "r"(b0), "r"(b1));
}

constexpr int M_CONV1 = 0, M_PLAIN = 1, M_K1 = 2, M_K2 = 3, M_K3 = 4, M_K4 = 5;

template <int MODE>
__device__ __forceinline__ void epi_row(int gm, int gc, float v0, float v1,
                                        const float* __restrict__ bias) {
    if (gm >= NN) return;
    if constexpr (MODE == M_CONV1) {
        if (gc < 128) g_uv1[(size_t)gm * 64 + (gc >> 1)] = pk(v0, v1);
        else { g_r1[(size_t)gm * 64 + gc - 128] = v0; g_r1[(size_t)gm * 64 + gc - 127] = v1; }
    } else if constexpr (MODE == M_PLAIN) {
        g_a16[(size_t)gm * 32 + (gc >> 1)] = pk(v0 + bias[gc], v1 + bias[gc + 1]);
    } else if constexpr (MODE == M_K1) {
        size_t ix = (size_t)gm * 64 + gc;
        float k0 = v0 + bias[gc], k1 = v1 + bias[gc + 1];
        float h0 = g_hf[ix], h1 = g_hf[ix + 1];
        g_y16[(size_t)gm * 32 + (gc >> 1)] = pk(h0 + 1.5f * k0, h1 + 1.5f * k1);
        g_accf[ix] = h0 + 0.5f * k0; g_accf[ix + 1] = h1 + 0.5f * k1;
    } else if constexpr (MODE == M_K2) {
        size_t ix = (size_t)gm * 64 + gc;
        float k0 = v0 + bias[gc], k1 = v1 + bias[gc + 1];
        float h0 = g_hf[ix], h1 = g_hf[ix + 1];
        g_y16[(size_t)gm * 32 + (gc >> 1)] = pk(h0 + 1.5f * k0, h1 + 1.5f * k1);
        g_accf[ix] += k0; g_accf[ix + 1] += k1;
    } else if constexpr (MODE == M_K3) {
        size_t ix = (size_t)gm * 64 + gc;
        float k0 = v0 + bias[gc], k1 = v1 + bias[gc + 1];
        float h0 = g_hf[ix], h1 = g_hf[ix + 1];
        g_y16[(size_t)gm * 32 + (gc >> 1)] = pk(h0 + 3.0f * k0, h1 + 3.0f * k1);
        g_accf[ix] += k0; g_accf[ix + 1] += k1;
    }
}

// conv1 GEMM: A register-prefetch pipeline, direct B smem fill (L2-hot weights),
// 3 blocks/SM target. trig at entry; trailing gds joins scatter.
template <int K, int NOUT, int BN, int MODE>
__global__ __launch_bounds__(256, 3)
void gemm16(const float* __restrict__ bias) {
    trig();
    constexpr int NF = BN / 16;
    __shared__ __align__(16) unsigned As[128][36];
    __shared__ unsigned Bs[32][72];

    const unsigned* Wp = g_wc1;

    const int tid = threadIdx.x;
    const int m0 = blockIdx.x * 128;
    const int n0 = blockIdx.y * BN;
    const int wid = tid >> 5, lane = tid & 31;
    const int wm = (wid & 3) * 32;
    const int wn = (wid >> 2) * (BN / 2);
    const int g = lane >> 2, t = lane & 3;

    float acc[2][NF][4];
    #pragma unroll
    for (int i = 0; i < 2; i++)
        #pragma unroll
        for (int j = 0; j < NF; j++)
            #pragma unroll
            for (int e = 0; e < 4; e++) acc[i][j][e] = 0.f;

    uint4 aReg[4];
    auto loadA = [&](int kc) {
        #pragma unroll
        for (int i = 0; i < 4; i++) {
            int q = tid + i * 256;
            int row = q >> 3, q4 = q & 7;
            int gm = m0 + row;
            int gmc = gm < NN ? gm : NN - 1;   // clamp: unconditional load
            aReg[i] = *reinterpret_cast<const uint4*>(
                          g_x16 + (size_t)gmc * 128 + kc / 2 + q4 * 4);
        }
    };

    loadA(0);
    for (int kc = 0; kc < K; kc += 64) {
        __syncthreads();   // previous chunk's mma reads finished
        #pragma unroll
        for (int i = 0; i < 4; i++) {
            int q = tid + i * 256;
            *reinterpret_cast<uint4*>(&As[q >> 3][(q & 7) * 4]) = aReg[i];
        }
        #pragma unroll
        for (int i = 0; i < 8; i++) {
            int q = tid + i * 256;
            int r = q >> 6, n = q & 63;
            Bs[r][n] = Wp[(size_t)(kc / 2 + r) * NOUT + n0 + n];
        }
        if (kc + 64 < K) loadA(kc + 64);   // overlaps mma below
        __syncthreads();
        #pragma unroll
        for (int ks = 0; ks < 4; ks++) {
            const int kb = ks * 8;
            unsigned a[2][4];
            #pragma unroll
            for (int mf = 0; mf < 2; mf++) {
                a[mf][0] = As[wm + mf * 16 + g    ][kb + t];
                a[mf][1] = As[wm + mf * 16 + g + 8][kb + t];
                a[mf][2] = As[wm + mf * 16 + g    ][kb + 4 + t];
                a[mf][3] = As[wm + mf * 16 + g + 8][kb + 4 + t];
            }
            unsigned b[NF][2];
            #pragma unroll
            for (int nf = 0; nf < NF; nf++) {
                b[nf][0] = Bs[kb + t    ][wn + nf * 8 + g];
                b[nf][1] = Bs[kb + 4 + t][wn + nf * 8 + g];
            }
            #pragma unroll
            for (int mf = 0; mf < 2; mf++)
                #pragma unroll
                for (int nf = 0; nf < NF; nf++)
                    mma16(acc[mf][nf], a[mf][0], a[mf][1], a[mf][2], a[mf][3],
                          b[nf][0], b[nf][1]);
        }
    }

    #pragma unroll
    for (int mf = 0; mf < 2; mf++)
        #pragma unroll
        for (int nf = 0; nf < NF; nf++) {
            int gm0 = m0 + wm + mf * 16 + g;
            int gc  = n0 + wn + nf * 8 + t * 2;
            epi_row<MODE>(gm0,     gc, acc[mf][nf][0], acc[mf][nf][1], bias);
            epi_row<MODE>(gm0 + 8, gc, acc[mf][nf][2], acc[mf][nf][3], bias);
        }
    gds();   // join with scatter: completion implies both
}

// ---------------- hidden GEMM: weight preload pre-gds + A register prefetch -------
// MODE == M_K4 additionally runs the fused conv2 GEMM on the fresh h_new tile.
template <int MODE, int WSEL, int YSEL>
__global__ __launch_bounds__(256)
void gemm_h(const float* __restrict__ bias) {
    trig();
    __shared__ __align__(16) unsigned As[128][36];
    __shared__ unsigned Bs[96][72];
    const unsigned* Wp = (WSEL == 1) ? g_wcA : g_wcB;
    const int tid = threadIdx.x;
    // preamble: full 96x64 weight matrix to smem (prep-sealed)
    #pragma unroll
    for (int i = 0; i < 24; i++) {
        int q = tid + i * 256;
        Bs[q >> 6][q & 63] = Wp[q];
    }
    gds();
    const unsigned* __restrict__ y = (YSEL == 0) ? g_h16 : (YSEL == 1) ? g_a16 : g_y16;
    const int m0 = blockIdx.x * 128;
    const int wid = tid >> 5, lane = tid & 31;
    const int wm = (wid & 3) * 32, wn = (wid >> 2) * 32;
    const int g = lane >> 2, t = lane & 3;

    float acc[2][4][4];
    #pragma unroll
    for (int i = 0; i < 2; i++)
        #pragma unroll
        for (int j = 0; j < 4; j++)
            #pragma unroll
            for (int e = 0; e < 4; e++) acc[i][j][e] = 0.f;

    uint4 aReg[4];
    auto loadA = [&](int chunk) {
        #pragma unroll
        for (int i = 0; i < 4; i++) {
            int q = tid + i * 256;
            int row = q >> 3, q4 = q & 7;
            int gm = m0 + row;
            int gmc = gm < NN ? gm : NN - 1;
            const unsigned* p = (chunk == 0) ? g_acat + (size_t)gmc * 64 + q4 * 4
                              : (chunk == 1) ? g_acat + (size_t)gmc * 64 + 32 + q4 * 4
                              :                y + (size_t)gmc * 32 + q4 * 4;
            aReg[i] = *reinterpret_cast<const uint4*>(p);
        }
    };

    loadA(0);
    #pragma unroll
    for (int chunk = 0; chunk < 3; chunk++) {
        __syncthreads();
        #pragma unroll
        for (int i = 0; i < 4; i++) {
            int q = tid + i * 256;
            *reinterpret_cast<uint4*>(&As[q >> 3][(q & 7) * 4]) = aReg[i];
        }
        if (chunk < 2) loadA(chunk + 1);   // overlaps mma below
        __syncthreads();
        const int c32 = chunk * 32;
        #pragma unroll
        for (int ks = 0; ks < 4; ks++) {
            const int kb = ks * 8;
            unsigned a[2][4];
            #pragma unroll
            for (int mf = 0; mf < 2; mf++) {
                a[mf][0] = As[wm + mf * 16 + g    ][kb + t];
                a[mf][1] = As[wm + mf * 16 + g + 8][kb + t];
                a[mf][2] = As[wm + mf * 16 + g    ][kb + 4 + t];
                a[mf][3] = As[wm + mf * 16 + g + 8][kb + 4 + t];
            }
            unsigned b[4][2];
            #pragma unroll
            for (int nf = 0; nf < 4; nf++) {
                b[nf][0] = Bs[c32 + kb + t    ][wn + nf * 8 + g];
                b[nf][1] = Bs[c32 + kb + 4 + t][wn + nf * 8 + g];
            }
            #pragma unroll
            for (int mf = 0; mf < 2; mf++)
                #pragma unroll
                for (int nf = 0; nf < 4; nf++)
                    mma16(acc[mf][nf], a[mf][0], a[mf][1], a[mf][2], a[mf][3],
                          b[nf][0], b[nf][1]);
        }
    }

    if constexpr (MODE != M_K4) {
        #pragma unroll
        for (int mf = 0; mf < 2; mf++)
            #pragma unroll
            for (int nf = 0; nf < 4; nf++) {
                int gm0 = m0 + wm + mf * 16 + g;
                int gc  = wn + nf * 8 + t * 2;
                epi_row<MODE>(gm0,     gc, acc[mf][nf][0], acc[mf][nf][1], bias);
                epi_row<MODE>(gm0 + 8, gc, acc[mf][nf][2], acc[mf][nf][3], bias);
            }
    } else {
        // ---- fused: h_new into As (bf16), then conv2 GEMM (K=64, N=48) ----
        __syncthreads();   // all mma reads of As/Bs done
        #pragma unroll
        for (int mf = 0; mf < 2; mf++)
            #pragma unroll
            for (int nf = 0; nf < 4; nf++) {
                #pragma unroll
                for (int half = 0; half < 2; half++) {
                    int row = wm + mf * 16 + g + half * 8;
                    int gm  = m0 + row;
                    int gc  = wn + nf * 8 + t * 2;
                    float hn0 = 0.f, hn1 = 0.f;
                    if (gm < NN) {
                        size_t ix = (size_t)gm * 64 + gc;
                        float k0 = acc[mf][nf][half * 2]     + bias[gc];
                        float k1 = acc[mf][nf][half * 2 + 1] + bias[gc + 1];
                        hn0 = g_accf[ix]     + 0.5f * k0;
                        hn1 = g_accf[ix + 1] + 0.5f * k1;
                    }
                    As[row][gc >> 1] = pk(hn0, hn1);
                }
            }
        #pragma unroll
        for (int i = 0; i < 6; i++) {
            int q = tid + i * 256;
            Bs[q / 48][q % 48] = g_wc2[q];
        }
        __syncthreads();

        const int wn2 = (wid >> 2) * 24;
        float a2[2][3][4];
        #pragma unroll
        for (int i = 0; i < 2; i++)
            #pragma unroll
            for (int j = 0; j < 3; j++)
                #pragma unroll
                for (int e = 0; e < 4; e++) a2[i][j][e] = 0.f;

        #pragma unroll
        for (int ks = 0; ks < 4; ks++) {
            const int kb = ks * 8;
            unsigned a[2][4];
            #pragma unroll
            for (int mf = 0; mf < 2; mf++) {
                a[mf][0] = As[wm + mf * 16 + g    ][kb + t];
                a[mf][1] = As[wm + mf * 16 + g + 8][kb + t];
                a[mf][2] = As[wm + mf * 16 + g    ][kb + 4 + t];
                a[mf][3] = As[wm + mf * 16 + g + 8][kb + 4 + t];
            }
            unsigned b[3][2];
            #pragma unroll
            for (int nf = 0; nf < 3; nf++) {
                b[nf][0] = Bs[kb + t    ][wn2 + nf * 8 + g];
                b[nf][1] = Bs[kb + 4 + t][wn2 + nf * 8 + g];
            }
            #pragma unroll
            for (int mf = 0; mf < 2; mf++)
                #pragma unroll
                for (int nf = 0; nf < 3; nf++)
                    mma16(a2[mf][nf], a[mf][0], a[mf][1], a[mf][2], a[mf][3],
                          b[nf][0], b[nf][1]);
        }

        #pragma unroll
        for (int mf = 0; mf < 2; mf++)
            #pragma unroll
            for (int nf = 0; nf < 3; nf++) {
                #pragma unroll
                for (int half = 0; half < 2; half++) {
                    int gm = m0 + wm + mf * 16 + g + half * 8;
                    int gc = wn2 + nf * 8 + t * 2;
                    if (gm >= NN) continue;
                    float v0 = a2[mf][nf][half * 2], v1 = a2[mf][nf][half * 2 + 1];
                    if (gc < 32) g_uv2[(size_t)gm * 16 + (gc >> 1)] = pk(v0, v1);
                    else { g_r2[(size_t)gm * 16 + gc - 32] = v0;
                           g_r2[(size_t)gm * 16 + gc - 31] = v1; }
                }
            }
    }
}

// ---------------- aggregation: warp per node, 4 edges/iter via 8-lane groups ------
// (all CSR reads strictly AFTER gds: the deep trig cascade may launch these
//  while k_scan is still running)
__global__ __launch_bounds__(256)
void agg_post1(const float* __restrict__ b1) {
    trig();
    gds();
    int node = (blockIdx.x << 3) + (threadIdx.x >> 5);
    int lane = threadIdx.x & 31;
    int lane8 = lane & 7, grp = lane >> 3;
    int beg = rp(node), end = rp(node + 1);
    float id = g_invdeg[node];
    float m[8];
    #pragma unroll
    for (int j = 0; j < 8; j++) m[j] = 0.f;

    auto body = [&](int e) {
        int2 E = g_edge[e];
        float p = __int_as_float(E.y), q = 1.f - p;
        const unsigned* row = g_uv1 + (size_t)E.x * 64 + lane8 * 4;
        uint4 U = *reinterpret_cast<const uint4*>(row);
        uint4 V = *reinterpret_cast<const uint4*>(row + 32);
        float2 u0 = up(U.x), u1 = up(U.y), u2 = up(U.z), u3 = up(U.w);
        float2 v0 = up(V.x), v1 = up(V.y), v2 = up(V.z), v3 = up(V.w);
        m[0] += q * u0.x + p * v0.x;  m[1] += q * u0.y + p * v0.y;
        m[2] += q * u1.x + p * v1.x;  m[3] += q * u1.y + p * v1.y;
        m[4] += q * u2.x + p * v2.x;  m[5] += q * u2.y + p * v2.y;
        m[6] += q * u3.x + p * v3.x;  m[7] += q * u3.y + p * v3.y;
    };

    int e = beg;
    for (; e + 8 <= end; e += 8) { body(e + grp); body(e + 4 + grp); }
    for (; e + 4 <= end; e += 4) body(e + grp);
    if (e + grp < end) body(e + grp);

    #pragma unroll
    for (int o = 8; o <= 16; o <<= 1)
        #pragma unroll
        for (int j = 0; j < 8; j++)
            m[j] += __shfl_xor_sync(0xffffffffu, m[j], o);

    if (grp == 0) {
        size_t ix = (size_t)node * 64 + lane8 * 8;
        float4 r0 = *reinterpret_cast<const float4*>(g_r1 + ix);
        float4 r1 = *reinterpret_cast<const float4*>(g_r1 + ix + 4);
        float h[8];
        #pragma unroll
        for (int j = 0; j < 8; j++) {
            float r = (j < 4) ? (&r0.x)[j] : (&r1.x)[j - 4];
            h[j] = tanhf(m[j] * id + r + b1[lane8 * 8 + j]);
        }
        *reinterpret_cast<float4*>(g_hf + ix)     = make_float4(h[0], h[1], h[2], h[3]);
        *reinterpret_cast<float4*>(g_hf + ix + 4) = make_float4(h[4], h[5], h[6], h[7]);
        uint4 o16 = make_uint4(pk(h[0], h[1]), pk(h[2], h[3]), pk(h[4], h[5]), pk(h[6], h[7]));
        *reinterpret_cast<uint4*>(g_h16 + (size_t)node * 32 + lane8 * 4) = o16;
    }
}

// hidden pre-agg: rows of y are 32 u32; one uint4 per group per edge.
template <int YSEL>  // 0=g_h16, 1=g_a16, 2=g_y16
__global__ __launch_bounds__(256)
void agg_pre() {
    trig();
    gds();
    int node = (blockIdx.x << 3) + (threadIdx.x >> 5);
    int lane = threadIdx.x & 31;
    int lane8 = lane & 7, grp = lane >> 3;
    int beg = rp(node), end = rp(node + 1);
    float id = g_invdeg[node];
    const unsigned* __restrict__ y = (YSEL == 0) ? g_h16 : (YSEL == 1) ? g_a16 : g_y16;
    float a0[8], a1[8];
    #pragma unroll
    for (int j = 0; j < 8; j++) { a0[j] = 0.f; a1[j] = 0.f; }

    auto body = [&](int e) {
        int2 E = g_edge[e];
        float p = __int_as_float(E.y), q = 1.f - p;
        uint4 v = *reinterpret_cast<const uint4*>(y + (size_t)E.x * 32 + lane8 * 4);
        float2 f0 = up(v.x), f1 = up(v.y), f2 = up(v.z), f3 = up(v.w);
        a0[0] += q * f0.x;  a0[1] += q * f0.y;  a0[2] += q * f1.x;  a0[3] += q * f1.y;
        a0[4] += q * f2.x;  a0[5] += q * f2.y;  a0[6] += q * f3.x;  a0[7] += q * f3.y;
        a1[0] += p * f0.x;  a1[1] += p * f0.y;  a1[2] += p * f1.x;  a1[3] += p * f1.y;
        a1[4] += p * f2.x;  a1[5] += p * f2.y;  a1[6] += p * f3.x;  a1[7] += p * f3.y;
    };

    int e = beg;
    for (; e + 8 <= end; e += 8) { body(e + grp); body(e + 4 + grp); }
    for (; e + 4 <= end; e += 4) body(e + grp);
    if (e + grp < end) body(e + grp);

    #pragma unroll
    for (int o = 8; o <= 16; o <<= 1)
        #pragma unroll
        for (int j = 0; j < 8; j++) {
            a0[j] += __shfl_xor_sync(0xffffffffu, a0[j], o);
            a1[j] += __shfl_xor_sync(0xffffffffu, a1[j], o);
        }

    if (grp == 0) {
        uint4 o0 = make_uint4(pk(a0[0] * id, a0[1] * id), pk(a0[2] * id, a0[3] * id),
                              pk(a0[4] * id, a0[5] * id), pk(a0[6] * id, a0[7] * id));
        uint4 o1 = make_uint4(pk(a1[0] * id, a1[1] * id), pk(a1[2] * id, a1[3] * id),
                              pk(a1[4] * id, a1[5] * id), pk(a1[6] * id, a1[7] * id));
        *reinterpret_cast<uint4*>(g_acat + (size_t)node * 64 + lane8 * 4)      = o0;
        *reinterpret_cast<uint4*>(g_acat + (size_t)node * 64 + 32 + lane8 * 4) = o1;
    }
}

// conv2: gather + tanh + log_softmax(16); 16 threads per node
__global__ __launch_bounds__(256)
void conv2_fin(const float* __restrict__ b2, float* __restrict__ out) {
    trig();
    gds();
    int node = blockIdx.x * 16 + (threadIdx.x >> 4);
    int c = threadIdx.x & 15;
    int beg = rp(node), end = rp(node + 1);
    float id = g_invdeg[node];
    float m = 0.f;
    int e = beg;
    for (; e + 2 <= end; e += 2) {
        int2 E0 = g_edge[e], E1 = g_edge[e + 1];
        float p0 = __int_as_float(E0.y), p1 = __int_as_float(E1.y);
        float u0 = bfh(g_uv2[(size_t)E0.x * 16 + (c >> 1)], c & 1);
        float v0 = bfh(g_uv2[(size_t)E0.x * 16 + 8 + (c >> 1)], c & 1);
        float u1 = bfh(g_uv2[(size_t)E1.x * 16 + (c >> 1)], c & 1);
        float v1 = bfh(g_uv2[(size_t)E1.x * 16 + 8 + (c >> 1)], c & 1);
        m += (1.f - p0) * u0 + p0 * v0 + (1.f - p1) * u1 + p1 * v1;
    }
    if (e < end) {
        int2 E0 = g_edge[e];
        float p0 = __int_as_float(E0.y);
        float u = bfh(g_uv2[(size_t)E0.x * 16 + (c >> 1)], c & 1);
        float v = bfh(g_uv2[(size_t)E0.x * 16 + 8 + (c >> 1)], c & 1);
        m += (1.f - p0) * u + p0 * v;
    }
    float o = tanhf(m * id + g_r2[(size_t)node * 16 + c] + b2[c]);
    float mx = o;
    #pragma unroll
    for (int k = 8; k; k >>= 1) mx = fmaxf(mx, __shfl_xor_sync(0xffffffffu, mx, k));
    float s = expf(o - mx);
    float tot = s;
    #pragma unroll
    for (int k = 8; k; k >>= 1) tot += __shfl_xor_sync(0xffffffffu, tot, k);
    out[(size_t)node * 16 + c] = o - mx - logf(tot);
}

// ---------------- launch helpers (PDL on every kernel) ----------------
template <typename F, typename... Args>
static inline void pdl(F f, dim3 grid, dim3 block, Args... args) {
    cudaLaunchConfig_t cfg = {};
    cfg.gridDim = grid;
    cfg.blockDim = block;
    cfg.dynamicSmemBytes = 0;
    cfg.stream = 0;
    cudaLaunchAttribute a[1];
    a[0].id = cudaLaunchAttributeProgrammaticStreamSerialization;
    a[0].val.programmaticStreamSerializationAllowed = 1;
    cfg.attrs = a;
    cfg.numAttrs = 1;
    cudaLaunchKernelEx(&cfg, f, args...);
}

extern "C" void kernel_launch(void* const* d_in, const int* in_sizes, int n_in,
                              void* d_out, int out_size) {
    const float* x   = (const float*)d_in[0];
    const float* ea  = (const float*)d_in[1];
    const int*   src = (const int*)  d_in[2];
    const int*   dst = (const int*)  d_in[3];
    const float* W1  = (const float*)d_in[4];
    const float* R1  = (const float*)d_in[5];
    const float* b1  = (const float*)d_in[6];
    const float* Wa  = (const float*)d_in[7];
    const float* Ra  = (const float*)d_in[8];
    const float* ba  = (const float*)d_in[9];
    const float* Wb  = (const float*)d_in[10];
    const float* Rb  = (const float*)d_in[11];
    const float* bb  = (const float*)d_in[12];
    const float* W2  = (const float*)d_in[13];
    const float* R2  = (const float*)d_in[14];
    const float* b2  = (const float*)d_in[15];
    float* out = (float*)d_out;

    // CSR build + weight/x prep
    pdl(k_prep, dim3(4057), dim3(256), dst, x, W1, R1, Wa, Ra, Wb, Rb, W2, R2);
    pdl(k_scan, dim3(49), dim3(1024));
    pdl(k_scatter, dim3(3125), dim3(256), src, dst, ea);

    dim3 g1(391, 3), gh(391, 1), ga(6250), gb(256);

    // conv1 GEMM: overlaps scan AND scatter (no leading gds); trailing gds joins
    pdl(gemm16<256, 192, 64, M_CONV1>, g1, gb, (const float*)nullptr);
    pdl(agg_post1, ga, gb, b1);

    // RK4: 8 (agg_pre + gemm_h) pairs; last gemm_h also does conv2's GEMM
    pdl(agg_pre<0>, ga, gb);
    pdl(gemm_h<M_PLAIN, 1, 0>, gh, gb, ba);
    pdl(agg_pre<1>, ga, gb);
    pdl(gemm_h<M_K1,    2, 1>, gh, gb, bb);

    pdl(agg_pre<2>, ga, gb);
    pdl(gemm_h<M_PLAIN, 1, 2>, gh, gb, ba);
    pdl(agg_pre<1>, ga, gb);
    pdl(gemm_h<M_K2,    2, 1>, gh, gb, bb);

    pdl(agg_pre<2>, ga, gb);
    pdl(gemm_h<M_PLAIN, 1, 2>, gh, gb, ba);
    pdl(agg_pre<1>, ga, gb);
    pdl(gemm_h<M_K3,    2, 1>, gh, gb, bb);

    pdl(agg_pre<2>, ga, gb);
    pdl(gemm_h<M_PLAIN, 1, 2>, gh, gb, ba);
    pdl(agg_pre<1>, ga, gb);
    pdl(gemm_h<M_K4,    2, 1>, gh, gb, bb);   // + fused conv2 GEMM

    // finish
    pdl(conv2_fin, dim3(3125), gb, b2, out);
}